// round 12
// baseline (speedup 1.0000x reference)
#include <cuda_runtime.h>
#include <cuda_bf16.h>
#include <cuda_fp16.h>
#include <math.h>
#include <stdint.h>

#define HEADS    16
#define DH       64
#define NSEQ     2048
#define BATCH    4
#define DIMIN    1024
#define HID      1024
#define ROWS     (BATCH*NSEQ)     // 8192
#define QKV_COLS (3*HID)          // 3072
#define BH       (BATCH*HEADS)    // 64
#define ATT_SCALE 0.125f
#define NITILE   (NSEQ/128)       // 16

// swizzled smem: 32 k-elems/row = 64B rows, chunk c in 0..3, phys chunk = c ^ ((row>>1)&3)
#define MOFF  8192                // one 128x32 bf16/fp16 matrix
#define S4    32768               // 4-matrix stage (qkv/scores)
#define S3    24576               // 3-matrix stage (out)
#define QKV_SMEM (3*S4)           // 98304
#define SC_SMEM  (2*S4)           // 65536
#define OUT_SMEM (3*S3)           // 73728

// ---------------- static scratch ----------------
__device__ float g_rl[BH * NSEQ];                           // 1/colsum
__device__ float g_pcs[(size_t)BH * NITILE * NSEQ];         // partial col sums
__device__ __half g_P [(size_t)BH * NSEQ * NSEQ];           // P = exp(s), fp16
__device__ __half g_v [(size_t)ROWS * HID];                 // V, fp16
__device__ __half g_y [(size_t)ROWS * HID];                 // attention out, fp16
__device__ __nv_bfloat16 g_xh [(size_t)ROWS * DIMIN];
__device__ __nv_bfloat16 g_xl [(size_t)ROWS * DIMIN];
__device__ __nv_bfloat16 g_qkvh[(size_t)ROWS * QKV_COLS];   // only Q,K thirds used
__device__ __nv_bfloat16 g_qkvl[(size_t)ROWS * QKV_COLS];
__device__ __nv_bfloat16 g_wqh[(size_t)QKV_COLS * DIMIN];   // w_qkv^T hi  [N,K]
__device__ __nv_bfloat16 g_wql[(size_t)QKV_COLS * DIMIN];
__device__ __half g_woh[(size_t)DIMIN * HID];               // w_out^T hi  [N,K]
__device__ __half g_wol[(size_t)DIMIN * HID];               // w_out^T lo

// ---------------- helpers ----------------
__device__ __forceinline__ uint32_t smem_u32(const void* p) {
    uint32_t a;
    asm("{ .reg .u64 t; cvta.to.shared.u64 t, %1; cvt.u32.u64 %0, t; }"
        : "=r"(a) : "l"(p));
    return a;
}
__device__ __forceinline__ void cp_async16(uint32_t s, const void* g) {
    asm volatile("cp.async.cg.shared.global [%0], [%1], 16;" :: "r"(s), "l"(g));
}
#define CP_COMMIT() asm volatile("cp.async.commit_group;" ::: "memory")
template <int N>
__device__ __forceinline__ void cp_wait() {
    asm volatile("cp.async.wait_group %0;" :: "n"(N) : "memory");
}
#define LDM_X4(r, a)                                                        \
    asm volatile("ldmatrix.sync.aligned.m8n8.x4.shared.b16 {%0,%1,%2,%3}, [%4];" \
        : "=r"((r)[0]), "=r"((r)[1]), "=r"((r)[2]), "=r"((r)[3]) : "r"(a))

// ldmatrix address in swizzled layout. r0 must be a multiple of 16 (8 for V).
// ksb = (k elem offset)>>3 (0 or 2). lrow64 = (lane&15)*64; lc = lane>>4;
// lsw = ((lane&15)>>1)&3.
__device__ __forceinline__ uint32_t ldma(uint32_t mbase, int r0, int ksb,
                                         uint32_t lrow64, int lc, int lsw) {
    return mbase + (uint32_t)(r0 * 64) + lrow64 +
           (uint32_t)((((ksb + lc) ^ lsw)) << 4);
}

// mma.sync m16n8k16 bf16 (acc fp32)
__device__ __forceinline__ void mma_bf(float* c, const uint32_t* a,
                                       uint32_t b0, uint32_t b1) {
    asm volatile(
        "mma.sync.aligned.m16n8k16.row.col.f32.bf16.bf16.f32 "
        "{%0,%1,%2,%3}, {%4,%5,%6,%7}, {%8,%9}, {%0,%1,%2,%3};\n"
        : "+f"(c[0]), "+f"(c[1]), "+f"(c[2]), "+f"(c[3])
        : "r"(a[0]), "r"(a[1]), "r"(a[2]), "r"(a[3]), "r"(b0), "r"(b1));
}
// mma.sync m16n8k16 fp16 (acc fp32)
__device__ __forceinline__ void mma_f16(float* c, const uint32_t* a,
                                        uint32_t b0, uint32_t b1) {
    asm volatile(
        "mma.sync.aligned.m16n8k16.row.col.f32.f16.f16.f32 "
        "{%0,%1,%2,%3}, {%4,%5,%6,%7}, {%8,%9}, {%0,%1,%2,%3};\n"
        : "+f"(c[0]), "+f"(c[1]), "+f"(c[2]), "+f"(c[3])
        : "r"(a[0]), "r"(a[1]), "r"(a[2]), "r"(a[3]), "r"(b0), "r"(b1));
}

__device__ __forceinline__ void split2(float a, float b,
                                       __nv_bfloat162& hp, __nv_bfloat162& lp) {
    __nv_bfloat16 ha = __float2bfloat16(a), hb = __float2bfloat16(b);
    hp.x = ha; hp.y = hb;
    lp.x = __float2bfloat16(a - __bfloat162float(ha));
    lp.y = __float2bfloat16(b - __bfloat162float(hb));
}

// 4-matrix stage load (Ah/Al/Bh/Bl), 128 rows x 32 k each, swizzled.
__device__ __forceinline__ void stage_load4(uint32_t sbase,
    const __nv_bfloat16* Ah, const __nv_bfloat16* Al, int sA,
    const __nv_bfloat16* Bh, const __nv_bfloat16* Bl, int sB,
    int k0, int tid)
{
#pragma unroll
    for (int r = 0; r < 2; r++) {
        int sid = tid + (r << 8);
        int row = sid >> 2, seg = sid & 3;
        uint32_t so = sbase +
            (uint32_t)(row * 64 + ((seg ^ ((row >> 1) & 3)) << 4));
        size_t oa = (size_t)row * sA + k0 + seg * 8;
        size_t ob = (size_t)row * sB + k0 + seg * 8;
        cp_async16(so,              Ah + oa);
        cp_async16(so + 1 * MOFF,   Al + oa);
        cp_async16(so + 2 * MOFF,   Bh + ob);
        cp_async16(so + 3 * MOFF,   Bl + ob);
    }
}

// 3-pass bf16 compute of one 32-k chunk; warp tile 32(m) x 64(n)
__device__ __forceinline__ void mma_chunk3(uint32_t sb, int warp_m, int warp_n,
                                           uint32_t lrow64, int lc, int lsw,
                                           float acc[2][8][4]) {
    const uint32_t bAh = sb, bAl = sb + MOFF, bBh = sb + 2 * MOFF,
                   bBl = sb + 3 * MOFF;
#pragma unroll
    for (int ks = 0; ks < 32; ks += 16) {
        const int ksb = ks >> 3;
        uint32_t aH[2][4], aL[2][4];
#pragma unroll
        for (int mt = 0; mt < 2; mt++) {
            int r0 = warp_m * 32 + mt * 16;
            LDM_X4(aH[mt], ldma(bAh, r0, ksb, lrow64, lc, lsw));
            LDM_X4(aL[mt], ldma(bAl, r0, ksb, lrow64, lc, lsw));
        }
#pragma unroll
        for (int c = 0; c < 4; c++) {
            int n0 = warp_n * 64 + c * 16;
            uint32_t bh[4], bl[4];
            LDM_X4(bh, ldma(bBh, n0, ksb, lrow64, lc, lsw));
            LDM_X4(bl, ldma(bBl, n0, ksb, lrow64, lc, lsw));
#pragma unroll
            for (int half = 0; half < 2; half++) {
                int nt = c * 2 + half;
                uint32_t bh0 = bh[half], bh1 = bh[half + 2];
                uint32_t bl0 = bl[half], bl1 = bl[half + 2];
#pragma unroll
                for (int mt = 0; mt < 2; mt++) {
                    mma_bf(acc[mt][nt], aH[mt], bh0, bh1);
                    mma_bf(acc[mt][nt], aH[mt], bl0, bl1);
                    mma_bf(acc[mt][nt], aL[mt], bh0, bh1);
                }
            }
        }
    }
}

// =====================================================================
// QKV projection: Q/K tiles -> bf16 hi/lo; V -> fp16. 3-stage, 1 barrier.
// =====================================================================
__global__ __launch_bounds__(256, 2) void qkv_gemm() {
    extern __shared__ char smem[];
    const uint32_t sb32 = smem_u32(smem);
    const int tid = threadIdx.x, lane = tid & 31, wid = tid >> 5;
    const int warp_m = wid & 3, warp_n = wid >> 2;
    const int g = lane >> 2, ti = lane & 3;
    const uint32_t lrow64 = (uint32_t)((lane & 15) * 64);
    const int lc = lane >> 4, lsw = ((lane & 15) >> 1) & 3;
    const int bm = blockIdx.y * 128, bn = blockIdx.x * 128;
    const int K = DIMIN, N = QKV_COLS;

    const __nv_bfloat16* Ah0 = g_xh + (size_t)bm * K;
    const __nv_bfloat16* Al0 = g_xl + (size_t)bm * K;
    const __nv_bfloat16* Bh0 = g_wqh + (size_t)bn * K;
    const __nv_bfloat16* Bl0 = g_wql + (size_t)bn * K;

    float acc[2][8][4] = {};
    const int NT = K >> 5;   // 32

    stage_load4(sb32,      Ah0, Al0, K, Bh0, Bl0, K,  0, tid); CP_COMMIT();
    stage_load4(sb32 + S4, Ah0, Al0, K, Bh0, Bl0, K, 32, tid); CP_COMMIT();

    for (int kt = 0; kt < NT; kt++) {
        cp_wait<1>();
        __syncthreads();
        if (kt + 2 < NT)
            stage_load4(sb32 + ((kt + 2) % 3) * S4, Ah0, Al0, K, Bh0, Bl0, K,
                        (kt + 2) << 5, tid);
        CP_COMMIT();
        mma_chunk3(sb32 + (kt % 3) * S4, warp_m, warp_n, lrow64, lc, lsw, acc);
    }

    const bool isV = (bn >= 2 * HID);
#pragma unroll
    for (int mt = 0; mt < 2; mt++) {
        int r0 = bm + warp_m * 32 + mt * 16 + g;
#pragma unroll
        for (int nt = 0; nt < 8; nt++) {
            int col = bn + warp_n * 64 + nt * 8 + ti * 2;
            float v0 = acc[mt][nt][0], v1 = acc[mt][nt][1];
            float v2 = acc[mt][nt][2], v3 = acc[mt][nt][3];
            if (isV) {
                int cv = col - 2 * HID;
                __half2 w0; w0.x = __float2half(v0); w0.y = __float2half(v1);
                __half2 w1; w1.x = __float2half(v2); w1.y = __float2half(v3);
                *(__half2*)(g_v + (size_t)r0 * HID + cv)       = w0;
                *(__half2*)(g_v + (size_t)(r0 + 8) * HID + cv) = w1;
            } else {
                __nv_bfloat162 hp, lp;
                split2(v0, v1, hp, lp);
                *(__nv_bfloat162*)(g_qkvh + (size_t)r0 * N + col) = hp;
                *(__nv_bfloat162*)(g_qkvl + (size_t)r0 * N + col) = lp;
                split2(v2, v3, hp, lp);
                *(__nv_bfloat162*)(g_qkvh + (size_t)(r0 + 8) * N + col) = hp;
                *(__nv_bfloat162*)(g_qkvl + (size_t)(r0 + 8) * N + col) = lp;
            }
        }
    }
}

// =====================================================================
// scores: P = exp(scale*q.k) -> fp16; per-tile column partial sums.
// 2 chunks only; 2-stage.
// =====================================================================
__global__ __launch_bounds__(256, 2) void scores_mma() {
    extern __shared__ char smem[];
    const uint32_t sb32 = smem_u32(smem);
    const int tid = threadIdx.x, lane = tid & 31, wid = tid >> 5;
    const int warp_m = wid & 3, warp_n = wid >> 2;
    const int g = lane >> 2, ti = lane & 3;
    const uint32_t lrow64 = (uint32_t)((lane & 15) * 64);
    const int lc = lane >> 4, lsw = ((lane & 15) >> 1) & 3;

    const int bh = blockIdx.z;
    const int b = bh >> 4, h = bh & 15;
    const int i0 = blockIdx.y * 128;
    const int j0 = blockIdx.x * 128;

    const size_t qoff = (size_t)(b * NSEQ) * QKV_COLS + h * DH;
    const __nv_bfloat16* Qh = g_qkvh + qoff + (size_t)i0 * QKV_COLS;
    const __nv_bfloat16* Ql = g_qkvl + qoff + (size_t)i0 * QKV_COLS;
    const __nv_bfloat16* Kh = g_qkvh + qoff + HID + (size_t)j0 * QKV_COLS;
    const __nv_bfloat16* Kl = g_qkvl + qoff + HID + (size_t)j0 * QKV_COLS;

    float acc[2][8][4] = {};

    stage_load4(sb32,      Qh, Ql, QKV_COLS, Kh, Kl, QKV_COLS,  0, tid);
    CP_COMMIT();
    stage_load4(sb32 + S4, Qh, Ql, QKV_COLS, Kh, Kl, QKV_COLS, 32, tid);
    CP_COMMIT();
#pragma unroll
    for (int kt = 0; kt < 2; kt++) {
        if (kt == 0) cp_wait<1>(); else cp_wait<0>();
        __syncthreads();
        mma_chunk3(sb32 + kt * S4, warp_m, warp_n, lrow64, lc, lsw, acc);
        __syncthreads();
    }

    __half* P = g_P + (size_t)bh * NSEQ * NSEQ;
    float cs[8][2];
#pragma unroll
    for (int nt = 0; nt < 8; nt++) { cs[nt][0] = 0.f; cs[nt][1] = 0.f; }

#pragma unroll
    for (int mt = 0; mt < 2; mt++) {
        int r0 = i0 + warp_m * 32 + mt * 16 + g;
#pragma unroll
        for (int nt = 0; nt < 8; nt++) {
            int col = j0 + warp_n * 64 + nt * 8 + ti * 2;
            __half h0 = __float2half(__expf(acc[mt][nt][0] * ATT_SCALE));
            __half h1 = __float2half(__expf(acc[mt][nt][1] * ATT_SCALE));
            __half h2 = __float2half(__expf(acc[mt][nt][2] * ATT_SCALE));
            __half h3 = __float2half(__expf(acc[mt][nt][3] * ATT_SCALE));
            cs[nt][0] += __half2float(h0) + __half2float(h2);
            cs[nt][1] += __half2float(h1) + __half2float(h3);
            __half2 w0; w0.x = h0; w0.y = h1;
            __half2 w1; w1.x = h2; w1.y = h3;
            *(__half2*)(P + (size_t)r0 * NSEQ + col)       = w0;
            *(__half2*)(P + (size_t)(r0 + 8) * NSEQ + col) = w1;
        }
    }

#pragma unroll
    for (int nt = 0; nt < 8; nt++) {
#pragma unroll
        for (int e = 0; e < 2; e++) {
            float v = cs[nt][e];
            v += __shfl_xor_sync(0xFFFFFFFF, v, 4);
            v += __shfl_xor_sync(0xFFFFFFFF, v, 8);
            v += __shfl_xor_sync(0xFFFFFFFF, v, 16);
            cs[nt][e] = v;
        }
    }
    float* spart = (float*)smem;
    if (g == 0) {
#pragma unroll
        for (int nt = 0; nt < 8; nt++) {
            spart[warp_m * 128 + warp_n * 64 + nt * 8 + ti * 2]     = cs[nt][0];
            spart[warp_m * 128 + warp_n * 64 + nt * 8 + ti * 2 + 1] = cs[nt][1];
        }
    }
    __syncthreads();
    if (tid < 128) {
        float s = spart[tid] + spart[128 + tid] + spart[256 + tid] + spart[384 + tid];
        g_pcs[((size_t)bh * NITILE + blockIdx.y) * NSEQ + j0 + tid] = s;
    }
}

// =====================================================================
// rsum: rl[bh][j] = 1 / sum_itile pcs
// =====================================================================
__global__ void rsum_kernel() {
    const int bh = blockIdx.y;
    const int j = blockIdx.x * 256 + threadIdx.x;
    const float* p = g_pcs + (size_t)bh * NITILE * NSEQ + j;
    float s = 0.f;
#pragma unroll
    for (int t = 0; t < NITILE; t++) s += p[(size_t)t * NSEQ];
    g_rl[bh * NSEQ + j] = 1.0f / s;
}

// =====================================================================
// av: Y = P_fp16 @ diag(rl) V_fp16, 1-pass fp16.
// 3-stage P (cp.async) + 3-stage V (plain stores), single barrier per iter.
// smem: P 3x8192 | V 3x4096 = 36864
// =====================================================================
__global__ __launch_bounds__(256, 2) void av_mma() {
    __shared__ __align__(16) char sm[36864];
    const uint32_t sb32 = smem_u32(sm);
    const uint32_t vb32 = sb32 + 24576;

    const int tid = threadIdx.x, lane = tid & 31, wid = tid >> 5;
    const int g = lane >> 2, ti = lane & 3;
    const uint32_t lrow64 = (uint32_t)((lane & 15) * 64);
    const int lc = lane >> 4, lsw = ((lane & 15) >> 1) & 3;

    const int bh = blockIdx.y;
    const int b = bh >> 4, h = bh & 15;
    const int i0 = blockIdx.x * 128;

    const __half* Pg = g_P + (size_t)bh * NSEQ * NSEQ + (size_t)i0 * NSEQ;
    const __half* Vbase = g_v + (size_t)(b * NSEQ) * HID + h * DH;
    const float* rl = g_rl + bh * NSEQ;

    const int jl = tid >> 3;            // 0..31  (V j-row)
    const int d0 = (tid & 7) * 8;       // V d group

    auto loadP = [&](int s, int j0) {
#pragma unroll
        for (int r = 0; r < 2; r++) {
            int sid = tid + (r << 8);
            int row = sid >> 2, seg = sid & 3;
            uint32_t so = sb32 + (uint32_t)(s * 8192) +
                (uint32_t)(row * 64 + ((seg ^ ((row >> 1) & 3)) << 4));
            cp_async16(so, Pg + (size_t)row * NSEQ + j0 + seg * 8);
        }
    };
    // V stored [d][j]: 64 rows x 32 j, swizzled; rl folded in.
    auto writeV = [&](int s, int j0) {
        const float inv = rl[j0 + jl];
        const __half* Vr = Vbase + (size_t)(j0 + jl) * HID + d0;
        __half hv[8];
        *(float4*)hv = *(const float4*)Vr;
        char* vb = sm + 24576 + s * 4096;
#pragma unroll
        for (int e = 0; e < 8; e++) {
            float val = __half2float(hv[e]) * inv;
            int off = (d0 + e) * 64 + ((((jl >> 3) ^ ((e >> 1) & 3))) << 4) +
                      (jl & 7) * 2;
            *(__half*)(vb + off) = __float2half(val);
        }
    };

    float acc[8][4] = {};
    const int NJC = NSEQ / 32;          // 64

    loadP(0, 0);  CP_COMMIT();
    loadP(1, 32); CP_COMMIT();
    writeV(0, 0);
    writeV(1, 32);

    for (int jc = 0; jc < NJC; jc++) {
        cp_wait<1>();
        __syncthreads();
        if (jc + 2 < NJC) loadP((jc + 2) % 3, 32 * (jc + 2));
        CP_COMMIT();
        if (jc + 2 < NJC) writeV((jc + 2) % 3, 32 * (jc + 2));

        const uint32_t Pst = sb32 + (uint32_t)((jc % 3) * 8192);
        const uint32_t Vst = vb32 + (uint32_t)((jc % 3) * 4096);
#pragma unroll
        for (int ks = 0; ks < 32; ks += 16) {
            const int ksb = ks >> 3;
            uint32_t aP[4];
            LDM_X4(aP, ldma(Pst, wid * 16, ksb, lrow64, lc, lsw));
#pragma unroll
            for (int c = 0; c < 4; c++) {
                uint32_t bv[4];
                LDM_X4(bv, ldma(Vst, c * 16, ksb, lrow64, lc, lsw));
#pragma unroll
                for (int half = 0; half < 2; half++)
                    mma_f16(acc[c * 2 + half], aP, bv[half], bv[half + 2]);
            }
        }
    }

    // epilogue: write y fp16
    const int irow = i0 + wid * 16 + g;
#pragma unroll
    for (int nt = 0; nt < 8; nt++) {
        int d = nt * 8 + ti * 2;
        size_t o0 = (size_t)(b * NSEQ + irow) * HID + h * DH + d;
        size_t o1 = (size_t)(b * NSEQ + irow + 8) * HID + h * DH + d;
        __half2 w0; w0.x = __float2half(acc[nt][0]); w0.y = __float2half(acc[nt][1]);
        __half2 w1; w1.x = __float2half(acc[nt][2]); w1.y = __float2half(acc[nt][3]);
        *(__half2*)(g_y + o0) = w0;
        *(__half2*)(g_y + o1) = w1;
    }
}

// =====================================================================
// out-proj: out = y_fp16 @ (w_out^T fp16 hi/lo)^T + bias. 2-pass fp16.
// 3-stage (3 matrices/stage), single barrier per chunk.
// =====================================================================
__global__ __launch_bounds__(256, 2) void out_gemm(float* __restrict__ C,
                                                   const float* __restrict__ bias) {
    extern __shared__ char smem[];
    const uint32_t sb32 = smem_u32(smem);
    const int tid = threadIdx.x, lane = tid & 31, wid = tid >> 5;
    const int warp_m = wid & 3, warp_n = wid >> 2;
    const int g = lane >> 2, ti = lane & 3;
    const uint32_t lrow64 = (uint32_t)((lane & 15) * 64);
    const int lc = lane >> 4, lsw = ((lane & 15) >> 1) & 3;
    const int bm = blockIdx.y * 128, bn = blockIdx.x * 128;
    const int K = HID, N = DIMIN;

    const __half* A0  = g_y   + (size_t)bm * K;
    const __half* Bh0 = g_woh + (size_t)bn * K;
    const __half* Bl0 = g_wol + (size_t)bn * K;

    float acc[2][8][4] = {};
    const int NT = K >> 5;   // 32

    auto stage = [&](uint32_t sbase, int k0) {
#pragma unroll
        for (int r = 0; r < 2; r++) {
            int sid = tid + (r << 8);
            int row = sid >> 2, seg = sid & 3;
            uint32_t so = sbase +
                (uint32_t)(row * 64 + ((seg ^ ((row >> 1) & 3)) << 4));
            size_t oa = (size_t)row * K + k0 + seg * 8;
            cp_async16(so,            A0  + oa);
            cp_async16(so + 1 * MOFF, Bh0 + oa);
            cp_async16(so + 2 * MOFF, Bl0 + oa);
        }
    };

    stage(sb32,      0);  CP_COMMIT();
    stage(sb32 + S3, 32); CP_COMMIT();

    for (int kt = 0; kt < NT; kt++) {
        cp_wait<1>();
        __syncthreads();
        if (kt + 2 < NT) stage(sb32 + ((kt + 2) % 3) * S3, (kt + 2) << 5);
        CP_COMMIT();

        const uint32_t sb = sb32 + (kt % 3) * S3;
        const uint32_t bA = sb, bBh = sb + MOFF, bBl = sb + 2 * MOFF;
#pragma unroll
        for (int ks = 0; ks < 32; ks += 16) {
            const int ksb = ks >> 3;
            uint32_t aF[2][4];
#pragma unroll
            for (int mt = 0; mt < 2; mt++)
                LDM_X4(aF[mt], ldma(bA, warp_m * 32 + mt * 16, ksb, lrow64, lc, lsw));
#pragma unroll
            for (int c = 0; c < 4; c++) {
                int n0 = warp_n * 64 + c * 16;
                uint32_t bh[4], bl[4];
                LDM_X4(bh, ldma(bBh, n0, ksb, lrow64, lc, lsw));
                LDM_X4(bl, ldma(bBl, n0, ksb, lrow64, lc, lsw));
#pragma unroll
                for (int half = 0; half < 2; half++) {
                    int nt = c * 2 + half;
#pragma unroll
                    for (int mt = 0; mt < 2; mt++) {
                        mma_f16(acc[mt][nt], aF[mt], bh[half], bh[half + 2]);
                        mma_f16(acc[mt][nt], aF[mt], bl[half], bl[half + 2]);
                    }
                }
            }
        }
    }

#pragma unroll
    for (int mt = 0; mt < 2; mt++) {
        int r0 = bm + warp_m * 32 + mt * 16 + g;
#pragma unroll
        for (int nt = 0; nt < 8; nt++) {
            int col = bn + warp_n * 64 + nt * 8 + ti * 2;
            float2 bb = *(const float2*)(bias + col);
            *(float2*)(C + (size_t)r0 * N + col) =
                make_float2(acc[mt][nt][0] + bb.x, acc[mt][nt][1] + bb.y);
            *(float2*)(C + (size_t)(r0 + 8) * N + col) =
                make_float2(acc[mt][nt][2] + bb.x, acc[mt][nt][3] + bb.y);
        }
    }
}

// =====================================================================
// split fp32 -> bf16 hi/lo (elementwise)
// =====================================================================
__global__ void split_kernel(const float* __restrict__ in,
                             __nv_bfloat16* __restrict__ hi,
                             __nv_bfloat16* __restrict__ lo, size_t n4) {
    size_t i = (size_t)blockIdx.x * blockDim.x + threadIdx.x;
    if (i >= n4) return;
    float4 v = ((const float4*)in)[i];
    __nv_bfloat162 hp0, hp1, lp0, lp1;
    split2(v.x, v.y, hp0, lp0);
    split2(v.z, v.w, hp1, lp1);
    ((__nv_bfloat162*)hi)[i * 2 + 0] = hp0;
    ((__nv_bfloat162*)hi)[i * 2 + 1] = hp1;
    ((__nv_bfloat162*)lo)[i * 2 + 0] = lp0;
    ((__nv_bfloat162*)lo)[i * 2 + 1] = lp1;
}

// =====================================================================
// transpose + split: w[K,N] fp32 -> th/tl [N,K] bf16
// =====================================================================
__global__ void transpose_split_kernel(const float* __restrict__ w,
                                       __nv_bfloat16* __restrict__ th,
                                       __nv_bfloat16* __restrict__ tl,
                                       int K, int N) {
    __shared__ float tile[32][33];
    const int k0 = blockIdx.y * 32;
    const int n0 = blockIdx.x * 32;
    const int tx = threadIdx.x, ty = threadIdx.y;   // (32,8)
#pragma unroll
    for (int r = 0; r < 4; r++)
        tile[ty + 8 * r][tx] = w[(size_t)(k0 + ty + 8 * r) * N + n0 + tx];
    __syncthreads();
#pragma unroll
    for (int r = 0; r < 4; r++) {
        const int n = n0 + ty + 8 * r;
        const int k = k0 + tx;
        float v = tile[tx][ty + 8 * r];
        __nv_bfloat16 hh = __float2bfloat16(v);
        th[(size_t)n * K + k] = hh;
        tl[(size_t)n * K + k] = __float2bfloat16(v - __bfloat162float(hh));
    }
}

// transpose + split to fp16 hi/lo (for w_out)
__global__ void transpose_split_f16(const float* __restrict__ w,
                                    __half* __restrict__ th,
                                    __half* __restrict__ tl,
                                    int K, int N) {
    __shared__ float tile[32][33];
    const int k0 = blockIdx.y * 32;
    const int n0 = blockIdx.x * 32;
    const int tx = threadIdx.x, ty = threadIdx.y;   // (32,8)
#pragma unroll
    for (int r = 0; r < 4; r++)
        tile[ty + 8 * r][tx] = w[(size_t)(k0 + ty + 8 * r) * N + n0 + tx];
    __syncthreads();
#pragma unroll
    for (int r = 0; r < 4; r++) {
        const int n = n0 + ty + 8 * r;
        const int k = k0 + tx;
        float v = tile[tx][ty + 8 * r];
        __half hh = __float2half(v);
        th[(size_t)n * K + k] = hh;
        tl[(size_t)n * K + k] = __float2half(v - __half2float(hh));
    }
}

// ---------------------------------------------------------------------
extern "C" void kernel_launch(void* const* d_in, const int* in_sizes, int n_in,
                              void* d_out, int out_size) {
    const float* x     = (const float*)d_in[0];
    const float* w_qkv = (const float*)d_in[1];
    const float* w_out = (const float*)d_in[2];
    const float* b_out = (const float*)d_in[3];
    float* out = (float*)d_out;

    cudaFuncSetAttribute(qkv_gemm,
                         cudaFuncAttributeMaxDynamicSharedMemorySize, QKV_SMEM);
    cudaFuncSetAttribute(scores_mma,
                         cudaFuncAttributeMaxDynamicSharedMemorySize, SC_SMEM);
    cudaFuncSetAttribute(out_gemm,
                         cudaFuncAttributeMaxDynamicSharedMemorySize, OUT_SMEM);

    void *p_xh, *p_xl, *p_wqh, *p_wql, *p_woh, *p_wol;
    cudaGetSymbolAddress(&p_xh,  g_xh);
    cudaGetSymbolAddress(&p_xl,  g_xl);
    cudaGetSymbolAddress(&p_wqh, g_wqh);
    cudaGetSymbolAddress(&p_wql, g_wql);
    cudaGetSymbolAddress(&p_woh, g_woh);
    cudaGetSymbolAddress(&p_wol, g_wol);

    // 0a. split x -> bf16 hi/lo
    {
        size_t n4 = (size_t)ROWS * DIMIN / 4;
        split_kernel<<<(unsigned)((n4 + 255) / 256), 256>>>(
            x, (__nv_bfloat16*)p_xh, (__nv_bfloat16*)p_xl, n4);
    }
    // 0b. transpose+split w_qkv -> bf16 [N,K]
    transpose_split_kernel<<<dim3(QKV_COLS / 32, DIMIN / 32), dim3(32, 8)>>>(
        w_qkv, (__nv_bfloat16*)p_wqh, (__nv_bfloat16*)p_wql, DIMIN, QKV_COLS);
    // 0c. transpose+split w_out -> fp16 [N,K]
    transpose_split_f16<<<dim3(HID / 32, DIMIN / 32), dim3(32, 8)>>>(
        w_out, (__half*)p_woh, (__half*)p_wol, DIMIN, HID);

    // 1. QKV projection: Q/K -> bf16 hi/lo, V -> fp16
    qkv_gemm<<<dim3(QKV_COLS / 128, ROWS / 128), 256, QKV_SMEM>>>();

    // 2. P = exp(scale * Q K^T) (fp16) + partial column sums
    scores_mma<<<dim3(NSEQ / 128, NSEQ / 128, BH), 256, SC_SMEM>>>();

    // 3. rl = 1 / column sums
    rsum_kernel<<<dim3(NSEQ / 256, BH), 256>>>();

    // 4. Y = P diag(rl) V  -> y fp16
    av_mma<<<dim3(NSEQ / 128, BH), 256>>>();

    // 5. out = Y @ w_out + b_out (2-pass fp16)
    out_gemm<<<dim3(HID / 128, ROWS / 128), 256, OUT_SMEM>>>(out, b_out);
}

// round 13
// speedup vs baseline: 1.9233x; 1.9233x over previous
#include <cuda_runtime.h>
#include <cuda_bf16.h>
#include <cuda_fp16.h>
#include <math.h>
#include <stdint.h>

#define HEADS    16
#define DH       64
#define NSEQ     2048
#define BATCH    4
#define DIMIN    1024
#define HID      1024
#define ROWS     (BATCH*NSEQ)     // 8192
#define QKV_COLS (3*HID)          // 3072
#define BH       (BATCH*HEADS)    // 64
#define ATT_SCALE 0.125f
#define LDK      40               // padded k-stride (2B elems)  [proven layout]
#define NITILE   (NSEQ/128)       // 16
#define NQK      (2*HID)          // 2048 (Q|K row width)

// ---------------- static scratch ----------------
__device__ float g_rl[BH * NSEQ];                           // 1/colsum
__device__ float g_pcs[(size_t)BH * NITILE * NSEQ];         // partial col sums
__device__ __half g_P [(size_t)BH * NSEQ * NSEQ];           // P = exp(s), fp16
__device__ __half g_qk[(size_t)ROWS * NQK];                 // Q|K, single fp16
__device__ __half g_v [(size_t)ROWS * HID];                 // V, fp16
__device__ __half g_y [(size_t)ROWS * HID];                 // attention out, fp16
__device__ __nv_bfloat16 g_xh [(size_t)ROWS * DIMIN];
__device__ __nv_bfloat16 g_xl [(size_t)ROWS * DIMIN];
__device__ __nv_bfloat16 g_wqh[(size_t)QKV_COLS * DIMIN];   // w_qkv^T hi  [N,K]
__device__ __nv_bfloat16 g_wql[(size_t)QKV_COLS * DIMIN];
__device__ __half g_woh[(size_t)DIMIN * HID];               // w_out^T hi  [N,K]
__device__ __half g_wol[(size_t)DIMIN * HID];               // w_out^T lo

// ---------------- helpers ----------------
__device__ __forceinline__ uint32_t smem_u32(const void* p) {
    uint32_t a;
    asm("{ .reg .u64 t; cvta.to.shared.u64 t, %1; cvt.u32.u64 %0, t; }"
        : "=r"(a) : "l"(p));
    return a;
}
__device__ __forceinline__ void cp_async16(uint32_t s, const void* g) {
    asm volatile("cp.async.cg.shared.global [%0], [%1], 16;" :: "r"(s), "l"(g));
}
#define CP_COMMIT() asm volatile("cp.async.commit_group;" ::: "memory")
template <int N>
__device__ __forceinline__ void cp_wait() {
    asm volatile("cp.async.wait_group %0;" :: "n"(N) : "memory");
}
#define LDM_X4(r, a)                                                        \
    asm volatile("ldmatrix.sync.aligned.m8n8.x4.shared.b16 {%0,%1,%2,%3}, [%4];" \
        : "=r"((r)[0]), "=r"((r)[1]), "=r"((r)[2]), "=r"((r)[3]) : "r"(a))

// mma.sync m16n8k16 bf16 (acc fp32)
__device__ __forceinline__ void mma_bf(float* c, const uint32_t* a,
                                       uint32_t b0, uint32_t b1) {
    asm volatile(
        "mma.sync.aligned.m16n8k16.row.col.f32.bf16.bf16.f32 "
        "{%0,%1,%2,%3}, {%4,%5,%6,%7}, {%8,%9}, {%0,%1,%2,%3};\n"
        : "+f"(c[0]), "+f"(c[1]), "+f"(c[2]), "+f"(c[3])
        : "r"(a[0]), "r"(a[1]), "r"(a[2]), "r"(a[3]), "r"(b0), "r"(b1));
}
// mma.sync m16n8k16 fp16 (acc fp32)
__device__ __forceinline__ void mma_f16(float* c, const uint32_t* a,
                                        uint32_t b0, uint32_t b1) {
    asm volatile(
        "mma.sync.aligned.m16n8k16.row.col.f32.f16.f16.f32 "
        "{%0,%1,%2,%3}, {%4,%5,%6,%7}, {%8,%9}, {%0,%1,%2,%3};\n"
        : "+f"(c[0]), "+f"(c[1]), "+f"(c[2]), "+f"(c[3])
        : "r"(a[0]), "r"(a[1]), "r"(a[2]), "r"(a[3]), "r"(b0), "r"(b1));
}

__device__ __forceinline__ void split2(float a, float b,
                                       __nv_bfloat162& hp, __nv_bfloat162& lp) {
    __nv_bfloat16 ha = __float2bfloat16(a), hb = __float2bfloat16(b);
    hp.x = ha; hp.y = hb;
    lp.x = __float2bfloat16(a - __bfloat162float(ha));
    lp.y = __float2bfloat16(b - __bfloat162float(hb));
}

// stage layout (bytes): Ah 0 | Al 10240 | Bh 20480 | Bl 30720 ; stage 40960
#define STG 40960
#define DSMEM (2*STG)

__device__ __forceinline__ void stage_load(uint32_t sbase,
    const __nv_bfloat16* Ah, const __nv_bfloat16* Al, int sA,
    const __nv_bfloat16* Bh, const __nv_bfloat16* Bl, int sB,
    int k0, int tid)
{
#pragma unroll
    for (int r = 0; r < 2; r++) {
        int sid = tid + (r << 8);
        int row = sid >> 2, seg = sid & 3;
        uint32_t so = sbase + (uint32_t)(row * (LDK * 2) + seg * 16);
        size_t oa = (size_t)row * sA + k0 + seg * 8;
        size_t ob = (size_t)row * sB + k0 + seg * 8;
        cp_async16(so,          Ah + oa);
        cp_async16(so + 10240u, Al + oa);
        cp_async16(so + 20480u, Bh + ob);
        cp_async16(so + 30720u, Bl + ob);
    }
}

// 3-pass bf16 compute of one 32-k chunk; warp tile 32(m) x 64(n)
__device__ __forceinline__ void mma_chunk3(uint32_t sb, int warp_m, int warp_n,
                                           uint32_t ldm_off, float acc[2][8][4]) {
    const uint32_t bAh = sb, bAl = sb + 10240, bBh = sb + 20480, bBl = sb + 30720;
#pragma unroll
    for (int ks = 0; ks < 32; ks += 16) {
        uint32_t aH[2][4], aL[2][4];
#pragma unroll
        for (int mt = 0; mt < 2; mt++) {
            uint32_t ro = (uint32_t)((warp_m * 32 + mt * 16) * LDK + ks) * 2 + ldm_off;
            LDM_X4(aH[mt], bAh + ro);
            LDM_X4(aL[mt], bAl + ro);
        }
#pragma unroll
        for (int c = 0; c < 4; c++) {
            uint32_t bh[4], bl[4];
            uint32_t ro = (uint32_t)((warp_n * 64 + c * 16) * LDK + ks) * 2 + ldm_off;
            LDM_X4(bh, bBh + ro);
            LDM_X4(bl, bBl + ro);
#pragma unroll
            for (int half = 0; half < 2; half++) {
                int nt = c * 2 + half;
                uint32_t bh0 = bh[half], bh1 = bh[half + 2];
                uint32_t bl0 = bl[half], bl1 = bl[half + 2];
#pragma unroll
                for (int mt = 0; mt < 2; mt++) {
                    mma_bf(acc[mt][nt], aH[mt], bh0, bh1);
                    mma_bf(acc[mt][nt], aH[mt], bl0, bl1);
                    mma_bf(acc[mt][nt], aL[mt], bh0, bh1);
                }
            }
        }
    }
}

// =====================================================================
// QKV projection: Q/K tiles -> single fp16 into g_qk; V -> fp16 g_v.
// =====================================================================
__global__ __launch_bounds__(256, 2) void qkv_gemm() {
    extern __shared__ char smem[];
    const uint32_t sb32 = smem_u32(smem);
    const int tid = threadIdx.x, lane = tid & 31, wid = tid >> 5;
    const int warp_m = wid & 3, warp_n = wid >> 2;
    const int g = lane >> 2, ti = lane & 3;
    const uint32_t ldm_off =
        (uint32_t)((((lane >> 3) & 1) * 8 + (lane & 7)) * LDK + ((lane >> 4) * 8)) * 2;
    const int bm = blockIdx.y * 128, bn = blockIdx.x * 128;
    const int K = DIMIN;

    const __nv_bfloat16* Ah0 = g_xh + (size_t)bm * K;
    const __nv_bfloat16* Al0 = g_xl + (size_t)bm * K;
    const __nv_bfloat16* Bh0 = g_wqh + (size_t)bn * K;
    const __nv_bfloat16* Bl0 = g_wql + (size_t)bn * K;

    float acc[2][8][4] = {};
    const int NT = K >> 5;

    stage_load(sb32, Ah0, Al0, K, Bh0, Bl0, K, 0, tid);
    CP_COMMIT();
    for (int kt = 0; kt < NT; kt++) {
        if (kt + 1 < NT) {
            stage_load(sb32 + ((kt + 1) & 1) * STG, Ah0, Al0, K, Bh0, Bl0, K,
                       (kt + 1) << 5, tid);
            CP_COMMIT();
            cp_wait<1>();
        } else {
            cp_wait<0>();
        }
        __syncthreads();
        mma_chunk3(sb32 + (kt & 1) * STG, warp_m, warp_n, ldm_off, acc);
        __syncthreads();
    }

    const bool isV = (bn >= 2 * HID);
#pragma unroll
    for (int mt = 0; mt < 2; mt++) {
        int r0 = bm + warp_m * 32 + mt * 16 + g;
#pragma unroll
        for (int nt = 0; nt < 8; nt++) {
            int col = bn + warp_n * 64 + nt * 8 + ti * 2;
            __half2 w0, w1;
            w0.x = __float2half(acc[mt][nt][0]);
            w0.y = __float2half(acc[mt][nt][1]);
            w1.x = __float2half(acc[mt][nt][2]);
            w1.y = __float2half(acc[mt][nt][3]);
            if (isV) {
                int cv = col - 2 * HID;
                *(__half2*)(g_v + (size_t)r0 * HID + cv)       = w0;
                *(__half2*)(g_v + (size_t)(r0 + 8) * HID + cv) = w1;
            } else {
                *(__half2*)(g_qk + (size_t)r0 * NQK + col)       = w0;
                *(__half2*)(g_qk + (size_t)(r0 + 8) * NQK + col) = w1;
            }
        }
    }
}

// =====================================================================
// scores: P = exp(scale * q.k) -> fp16. 1-pass fp16 (Q,K single fp16).
// Stage: Q 10240 | K 10240 ; stage 20480, double-buffered.
// =====================================================================
#define SSTG 20480
#define SC_SMEM (2*SSTG)

__global__ __launch_bounds__(256, 2) void scores_mma() {
    extern __shared__ char smem[];
    const uint32_t sb32 = smem_u32(smem);
    const int tid = threadIdx.x, lane = tid & 31, wid = tid >> 5;
    const int warp_m = wid & 3, warp_n = wid >> 2;
    const int g = lane >> 2, ti = lane & 3;
    const uint32_t ldm_off =
        (uint32_t)((((lane >> 3) & 1) * 8 + (lane & 7)) * LDK + ((lane >> 4) * 8)) * 2;

    const int bh = blockIdx.z;
    const int b = bh >> 4, h = bh & 15;
    const int i0 = blockIdx.y * 128;
    const int j0 = blockIdx.x * 128;

    const __half* Q  = g_qk + (size_t)(b * NSEQ + i0) * NQK + h * DH;
    const __half* Kp = g_qk + (size_t)(b * NSEQ + j0) * NQK + HID + h * DH;

    auto stage2 = [&](uint32_t sbase, int k0) {
#pragma unroll
        for (int r = 0; r < 2; r++) {
            int sid = tid + (r << 8);
            int row = sid >> 2, seg = sid & 3;
            uint32_t so = sbase + (uint32_t)(row * (LDK * 2) + seg * 16);
            size_t oq = (size_t)row * NQK + k0 + seg * 8;
            cp_async16(so,          Q  + oq);
            cp_async16(so + 10240u, Kp + oq);
        }
    };

    float acc[2][8][4] = {};

    stage2(sb32,        0); CP_COMMIT();
    stage2(sb32 + SSTG, 32); CP_COMMIT();
#pragma unroll
    for (int kt = 0; kt < 2; kt++) {
        if (kt == 0) cp_wait<1>(); else cp_wait<0>();
        __syncthreads();
        const uint32_t bQ = sb32 + kt * SSTG, bK = bQ + 10240;
#pragma unroll
        for (int ks = 0; ks < 32; ks += 16) {
            uint32_t aQ[2][4];
#pragma unroll
            for (int mt = 0; mt < 2; mt++) {
                uint32_t ro = (uint32_t)((warp_m * 32 + mt * 16) * LDK + ks) * 2 + ldm_off;
                LDM_X4(aQ[mt], bQ + ro);
            }
#pragma unroll
            for (int c = 0; c < 4; c++) {
                uint32_t bk[4];
                uint32_t ro = (uint32_t)((warp_n * 64 + c * 16) * LDK + ks) * 2 + ldm_off;
                LDM_X4(bk, bK + ro);
#pragma unroll
                for (int half = 0; half < 2; half++) {
                    int nt = c * 2 + half;
#pragma unroll
                    for (int mt = 0; mt < 2; mt++)
                        mma_f16(acc[mt][nt], aQ[mt], bk[half], bk[half + 2]);
                }
            }
        }
        __syncthreads();
    }

    __half* P = g_P + (size_t)bh * NSEQ * NSEQ;
    float cs[8][2];
#pragma unroll
    for (int nt = 0; nt < 8; nt++) { cs[nt][0] = 0.f; cs[nt][1] = 0.f; }

#pragma unroll
    for (int mt = 0; mt < 2; mt++) {
        int r0 = i0 + warp_m * 32 + mt * 16 + g;
#pragma unroll
        for (int nt = 0; nt < 8; nt++) {
            int col = j0 + warp_n * 64 + nt * 8 + ti * 2;
            __half h0 = __float2half(__expf(acc[mt][nt][0] * ATT_SCALE));
            __half h1 = __float2half(__expf(acc[mt][nt][1] * ATT_SCALE));
            __half h2 = __float2half(__expf(acc[mt][nt][2] * ATT_SCALE));
            __half h3 = __float2half(__expf(acc[mt][nt][3] * ATT_SCALE));
            cs[nt][0] += __half2float(h0) + __half2float(h2);
            cs[nt][1] += __half2float(h1) + __half2float(h3);
            __half2 w0; w0.x = h0; w0.y = h1;
            __half2 w1; w1.x = h2; w1.y = h3;
            *(__half2*)(P + (size_t)r0 * NSEQ + col)       = w0;
            *(__half2*)(P + (size_t)(r0 + 8) * NSEQ + col) = w1;
        }
    }

#pragma unroll
    for (int nt = 0; nt < 8; nt++) {
#pragma unroll
        for (int e = 0; e < 2; e++) {
            float v = cs[nt][e];
            v += __shfl_xor_sync(0xFFFFFFFF, v, 4);
            v += __shfl_xor_sync(0xFFFFFFFF, v, 8);
            v += __shfl_xor_sync(0xFFFFFFFF, v, 16);
            cs[nt][e] = v;
        }
    }
    float* spart = (float*)smem;
    if (g == 0) {
#pragma unroll
        for (int nt = 0; nt < 8; nt++) {
            spart[warp_m * 128 + warp_n * 64 + nt * 8 + ti * 2]     = cs[nt][0];
            spart[warp_m * 128 + warp_n * 64 + nt * 8 + ti * 2 + 1] = cs[nt][1];
        }
    }
    __syncthreads();
    if (tid < 128) {
        float s = spart[tid] + spart[128 + tid] + spart[256 + tid] + spart[384 + tid];
        g_pcs[((size_t)bh * NITILE + blockIdx.y) * NSEQ + j0 + tid] = s;
    }
}

// =====================================================================
// rsum: rl[bh][j] = 1 / sum_itile pcs
// =====================================================================
__global__ void rsum_kernel() {
    const int bh = blockIdx.y;
    const int j = blockIdx.x * 256 + threadIdx.x;
    const float* p = g_pcs + (size_t)bh * NITILE * NSEQ + j;
    float s = 0.f;
#pragma unroll
    for (int t = 0; t < NITILE; t++) s += p[(size_t)t * NSEQ];
    g_rl[bh * NSEQ + j] = 1.0f / s;
}

// =====================================================================
// av: Y = P_fp16 @ diag(rl) V_fp16   1-pass fp16.  (round-11 proven)
// =====================================================================
__global__ __launch_bounds__(256, 2) void av_mma() {
    __shared__ __align__(16) char sm[15360]; // P 10240 | V 5120
    const uint32_t smP = smem_u32(sm);
    const uint32_t smV = smP + 10240;
    char* smVc = sm + 10240;

    const int tid = threadIdx.x, lane = tid & 31, wid = tid >> 5;
    const int g = lane >> 2, ti = lane & 3;
    const uint32_t ldm_off =
        (uint32_t)((((lane >> 3) & 1) * 8 + (lane & 7)) * LDK + ((lane >> 4) * 8)) * 2;

    const int bh = blockIdx.y;
    const int b = bh >> 4, h = bh & 15;
    const int i0 = blockIdx.x * 128;

    const __half* Pg = g_P + (size_t)bh * NSEQ * NSEQ + (size_t)i0 * NSEQ;
    const __half* Vbase = g_v + (size_t)(b * NSEQ) * HID + h * DH;
    const float* rl = g_rl + bh * NSEQ;

    const int jl = tid >> 3;            // 0..31  (V row)
    const int d0 = (tid & 7) * 8;       // V col group

    float acc[8][4] = {};

    for (int j0 = 0; j0 < NSEQ; j0 += 32) {
#pragma unroll
        for (int r = 0; r < 2; r++) {
            int sid = tid + (r << 8);
            int row = sid >> 2, seg = sid & 3;
            uint32_t so = (uint32_t)(row * (LDK * 2) + seg * 16);
            cp_async16(smP + so, Pg + (size_t)row * NSEQ + j0 + seg * 8);
        }
        CP_COMMIT();
        {
            const float inv = rl[j0 + jl];
            const __half* Vr = Vbase + (size_t)(j0 + jl) * HID + d0;
            __half2 v4[4];
            *(float4*)v4 = *(const float4*)Vr;
#pragma unroll
            for (int e = 0; e < 4; e++) {
                float lo = __half2float(v4[e].x) * inv;
                float hi = __half2float(v4[e].y) * inv;
                int off0 = ((d0 + e * 2)     * LDK + jl) * 2;
                int off1 = ((d0 + e * 2 + 1) * LDK + jl) * 2;
                *(__half*)(smVc + off0) = __float2half(lo);
                *(__half*)(smVc + off1) = __float2half(hi);
            }
        }
        cp_wait<0>();
        __syncthreads();

#pragma unroll
        for (int ks = 0; ks < 32; ks += 16) {
            uint32_t aP[4];
            uint32_t ro = (uint32_t)((wid * 16) * LDK + ks) * 2 + ldm_off;
            LDM_X4(aP, smP + ro);
#pragma unroll
            for (int c = 0; c < 4; c++) {
                uint32_t bv[4];
                uint32_t rb = (uint32_t)((c * 16) * LDK + ks) * 2 + ldm_off;
                LDM_X4(bv, smV + rb);
#pragma unroll
                for (int half = 0; half < 2; half++)
                    mma_f16(acc[c * 2 + half], aP, bv[half], bv[half + 2]);
            }
        }
        __syncthreads();
    }

    const int irow = i0 + wid * 16 + g;
#pragma unroll
    for (int nt = 0; nt < 8; nt++) {
        int d = nt * 8 + ti * 2;
        size_t o0 = (size_t)(b * NSEQ + irow) * HID + h * DH + d;
        size_t o1 = (size_t)(b * NSEQ + irow + 8) * HID + h * DH + d;
        __half2 w0; w0.x = __float2half(acc[nt][0]); w0.y = __float2half(acc[nt][1]);
        __half2 w1; w1.x = __float2half(acc[nt][2]); w1.y = __float2half(acc[nt][3]);
        *(__half2*)(g_y + o0) = w0;
        *(__half2*)(g_y + o1) = w1;
    }
}

// =====================================================================
// out-proj: out = y_fp16 @ (w_out^T fp16 hi/lo)^T + bias. 2-pass fp16.
// (round-11 proven)
// =====================================================================
#define OSTG 30720
#define ODSMEM (2*OSTG)

__global__ __launch_bounds__(256, 2) void out_gemm(float* __restrict__ C,
                                                   const float* __restrict__ bias) {
    extern __shared__ char smem[];
    const uint32_t sb32 = smem_u32(smem);
    const int tid = threadIdx.x, lane = tid & 31, wid = tid >> 5;
    const int warp_m = wid & 3, warp_n = wid >> 2;
    const int g = lane >> 2, ti = lane & 3;
    const uint32_t ldm_off =
        (uint32_t)((((lane >> 3) & 1) * 8 + (lane & 7)) * LDK + ((lane >> 4) * 8)) * 2;
    const int bm = blockIdx.y * 128, bn = blockIdx.x * 128;
    const int K = HID, N = DIMIN;

    const __half* A0  = g_y   + (size_t)bm * K;
    const __half* Bh0 = g_woh + (size_t)bn * K;
    const __half* Bl0 = g_wol + (size_t)bn * K;

    float acc[2][8][4] = {};
    const int NT = K >> 5;

    auto stage = [&](uint32_t sbase, int k0) {
#pragma unroll
        for (int r = 0; r < 2; r++) {
            int sid = tid + (r << 8);
            int row = sid >> 2, seg = sid & 3;
            uint32_t so = sbase + (uint32_t)(row * (LDK * 2) + seg * 16);
            size_t oa = (size_t)row * K + k0 + seg * 8;
            cp_async16(so,          A0  + oa);
            cp_async16(so + 10240u, Bh0 + oa);
            cp_async16(so + 20480u, Bl0 + oa);
        }
    };

    stage(sb32, 0);
    CP_COMMIT();
    for (int kt = 0; kt < NT; kt++) {
        if (kt + 1 < NT) {
            stage(sb32 + ((kt + 1) & 1) * OSTG, (kt + 1) << 5);
            CP_COMMIT();
            cp_wait<1>();
        } else {
            cp_wait<0>();
        }
        __syncthreads();
        const uint32_t sb = sb32 + (kt & 1) * OSTG;
        const uint32_t bA = sb, bBh = sb + 10240, bBl = sb + 20480;
#pragma unroll
        for (int ks = 0; ks < 32; ks += 16) {
            uint32_t aF[2][4];
#pragma unroll
            for (int mt = 0; mt < 2; mt++) {
                uint32_t ro = (uint32_t)((warp_m * 32 + mt * 16) * LDK + ks) * 2 + ldm_off;
                LDM_X4(aF[mt], bA + ro);
            }
#pragma unroll
            for (int c = 0; c < 4; c++) {
                uint32_t bh[4], bl[4];
                uint32_t ro = (uint32_t)((warp_n * 64 + c * 16) * LDK + ks) * 2 + ldm_off;
                LDM_X4(bh, bBh + ro);
                LDM_X4(bl, bBl + ro);
#pragma unroll
                for (int half = 0; half < 2; half++) {
                    int nt = c * 2 + half;
#pragma unroll
                    for (int mt = 0; mt < 2; mt++) {
                        mma_f16(acc[mt][nt], aF[mt], bh[half], bh[half + 2]);
                        mma_f16(acc[mt][nt], aF[mt], bl[half], bl[half + 2]);
                    }
                }
            }
        }
        __syncthreads();
    }

#pragma unroll
    for (int mt = 0; mt < 2; mt++) {
        int r0 = bm + warp_m * 32 + mt * 16 + g;
#pragma unroll
        for (int nt = 0; nt < 8; nt++) {
            int col = bn + warp_n * 64 + nt * 8 + ti * 2;
            float2 bb = *(const float2*)(bias + col);
            *(float2*)(C + (size_t)r0 * N + col) =
                make_float2(acc[mt][nt][0] + bb.x, acc[mt][nt][1] + bb.y);
            *(float2*)(C + (size_t)(r0 + 8) * N + col) =
                make_float2(acc[mt][nt][2] + bb.x, acc[mt][nt][3] + bb.y);
        }
    }
}

// =====================================================================
// split fp32 -> bf16 hi/lo (elementwise)
// =====================================================================
__global__ void split_kernel(const float* __restrict__ in,
                             __nv_bfloat16* __restrict__ hi,
                             __nv_bfloat16* __restrict__ lo, size_t n4) {
    size_t i = (size_t)blockIdx.x * blockDim.x + threadIdx.x;
    if (i >= n4) return;
    float4 v = ((const float4*)in)[i];
    __nv_bfloat162 hp0, hp1, lp0, lp1;
    split2(v.x, v.y, hp0, lp0);
    split2(v.z, v.w, hp1, lp1);
    ((__nv_bfloat162*)hi)[i * 2 + 0] = hp0;
    ((__nv_bfloat162*)hi)[i * 2 + 1] = hp1;
    ((__nv_bfloat162*)lo)[i * 2 + 0] = lp0;
    ((__nv_bfloat162*)lo)[i * 2 + 1] = lp1;
}

// =====================================================================
// transpose + split: w[K,N] fp32 -> th/tl [N,K] bf16
// =====================================================================
__global__ void transpose_split_kernel(const float* __restrict__ w,
                                       __nv_bfloat16* __restrict__ th,
                                       __nv_bfloat16* __restrict__ tl,
                                       int K, int N) {
    __shared__ float tile[32][33];
    const int k0 = blockIdx.y * 32;
    const int n0 = blockIdx.x * 32;
    const int tx = threadIdx.x, ty = threadIdx.y;   // (32,8)
#pragma unroll
    for (int r = 0; r < 4; r++)
        tile[ty + 8 * r][tx] = w[(size_t)(k0 + ty + 8 * r) * N + n0 + tx];
    __syncthreads();
#pragma unroll
    for (int r = 0; r < 4; r++) {
        const int n = n0 + ty + 8 * r;
        const int k = k0 + tx;
        float v = tile[tx][ty + 8 * r];
        __nv_bfloat16 hh = __float2bfloat16(v);
        th[(size_t)n * K + k] = hh;
        tl[(size_t)n * K + k] = __float2bfloat16(v - __bfloat162float(hh));
    }
}

// transpose + split to fp16 hi/lo (for w_out)
__global__ void transpose_split_f16(const float* __restrict__ w,
                                    __half* __restrict__ th,
                                    __half* __restrict__ tl,
                                    int K, int N) {
    __shared__ float tile[32][33];
    const int k0 = blockIdx.y * 32;
    const int n0 = blockIdx.x * 32;
    const int tx = threadIdx.x, ty = threadIdx.y;   // (32,8)
#pragma unroll
    for (int r = 0; r < 4; r++)
        tile[ty + 8 * r][tx] = w[(size_t)(k0 + ty + 8 * r) * N + n0 + tx];
    __syncthreads();
#pragma unroll
    for (int r = 0; r < 4; r++) {
        const int n = n0 + ty + 8 * r;
        const int k = k0 + tx;
        float v = tile[tx][ty + 8 * r];
        __half hh = __float2half(v);
        th[(size_t)n * K + k] = hh;
        tl[(size_t)n * K + k] = __float2half(v - __half2float(hh));
    }
}

// ---------------------------------------------------------------------
extern "C" void kernel_launch(void* const* d_in, const int* in_sizes, int n_in,
                              void* d_out, int out_size) {
    const float* x     = (const float*)d_in[0];
    const float* w_qkv = (const float*)d_in[1];
    const float* w_out = (const float*)d_in[2];
    const float* b_out = (const float*)d_in[3];
    float* out = (float*)d_out;

    cudaFuncSetAttribute(qkv_gemm,
                         cudaFuncAttributeMaxDynamicSharedMemorySize, DSMEM);
    cudaFuncSetAttribute(scores_mma,
                         cudaFuncAttributeMaxDynamicSharedMemorySize, SC_SMEM);
    cudaFuncSetAttribute(out_gemm,
                         cudaFuncAttributeMaxDynamicSharedMemorySize, ODSMEM);

    void *p_xh, *p_xl, *p_wqh, *p_wql, *p_woh, *p_wol;
    cudaGetSymbolAddress(&p_xh,  g_xh);
    cudaGetSymbolAddress(&p_xl,  g_xl);
    cudaGetSymbolAddress(&p_wqh, g_wqh);
    cudaGetSymbolAddress(&p_wql, g_wql);
    cudaGetSymbolAddress(&p_woh, g_woh);
    cudaGetSymbolAddress(&p_wol, g_wol);

    // 0a. split x -> bf16 hi/lo
    {
        size_t n4 = (size_t)ROWS * DIMIN / 4;
        split_kernel<<<(unsigned)((n4 + 255) / 256), 256>>>(
            x, (__nv_bfloat16*)p_xh, (__nv_bfloat16*)p_xl, n4);
    }
    // 0b. transpose+split w_qkv -> bf16 [N,K]
    transpose_split_kernel<<<dim3(QKV_COLS / 32, DIMIN / 32), dim3(32, 8)>>>(
        w_qkv, (__nv_bfloat16*)p_wqh, (__nv_bfloat16*)p_wql, DIMIN, QKV_COLS);
    // 0c. transpose+split w_out -> fp16 [N,K]
    transpose_split_f16<<<dim3(HID / 32, DIMIN / 32), dim3(32, 8)>>>(
        w_out, (__half*)p_woh, (__half*)p_wol, DIMIN, HID);

    // 1. QKV projection: Q/K -> fp16 g_qk, V -> fp16 g_v
    qkv_gemm<<<dim3(QKV_COLS / 128, ROWS / 128), 256, DSMEM>>>();

    // 2. P = exp(scale * Q K^T) (fp16, 1-pass) + partial column sums
    scores_mma<<<dim3(NSEQ / 128, NSEQ / 128, BH), 256, SC_SMEM>>>();

    // 3. rl = 1 / column sums
    rsum_kernel<<<dim3(NSEQ / 256, BH), 256>>>();

    // 4. Y = P diag(rl) V  -> y fp16
    av_mma<<<dim3(NSEQ / 128, BH), 256>>>();

    // 5. out = Y @ w_out + b_out (2-pass fp16)
    out_gemm<<<dim3(HID / 128, ROWS / 128), 256, ODSMEM>>>(out, b_out);
}

// round 14
// speedup vs baseline: 2.2014x; 1.1446x over previous
#include <cuda_runtime.h>
#include <cuda_fp16.h>
#include <math.h>
#include <stdint.h>

#define HEADS    16
#define DH       64
#define NSEQ     2048
#define BATCH    4
#define DIMIN    1024
#define HID      1024
#define ROWS     (BATCH*NSEQ)     // 8192
#define QKV_COLS (3*HID)          // 3072
#define BH       (BATCH*HEADS)    // 64
#define ATT_SCALE 0.125f
#define LDK      40               // padded k-stride (2B elems)  [proven layout]
#define NITILE   (NSEQ/128)       // 16
#define NQK      (2*HID)          // 2048 (Q|K row width)

// ---------------- static scratch ----------------
__device__ float g_rl[BH * NSEQ];                           // 1/colsum
__device__ float g_pcs[(size_t)BH * NITILE * NSEQ];         // partial col sums
__device__ __half g_P [(size_t)BH * NSEQ * NSEQ];           // P = exp(s), fp16
__device__ __half g_qk[(size_t)ROWS * NQK];                 // Q|K, fp16
__device__ __half g_v [(size_t)ROWS * HID];                 // V, fp16
__device__ __half g_y [(size_t)ROWS * HID];                 // attention out, fp16
__device__ __half g_x16[(size_t)ROWS * DIMIN];              // x, fp16
__device__ __half g_wqh[(size_t)QKV_COLS * DIMIN];          // w_qkv^T hi [N,K]
__device__ __half g_wql[(size_t)QKV_COLS * DIMIN];          // w_qkv^T lo
__device__ __half g_woh[(size_t)DIMIN * HID];               // w_out^T hi [N,K]
__device__ __half g_wol[(size_t)DIMIN * HID];               // w_out^T lo

// ---------------- helpers ----------------
__device__ __forceinline__ uint32_t smem_u32(const void* p) {
    uint32_t a;
    asm("{ .reg .u64 t; cvta.to.shared.u64 t, %1; cvt.u32.u64 %0, t; }"
        : "=r"(a) : "l"(p));
    return a;
}
__device__ __forceinline__ void cp_async16(uint32_t s, const void* g) {
    asm volatile("cp.async.cg.shared.global [%0], [%1], 16;" :: "r"(s), "l"(g));
}
#define CP_COMMIT() asm volatile("cp.async.commit_group;" ::: "memory")
template <int N>
__device__ __forceinline__ void cp_wait() {
    asm volatile("cp.async.wait_group %0;" :: "n"(N) : "memory");
}
#define LDM_X4(r, a)                                                        \
    asm volatile("ldmatrix.sync.aligned.m8n8.x4.shared.b16 {%0,%1,%2,%3}, [%4];" \
        : "=r"((r)[0]), "=r"((r)[1]), "=r"((r)[2]), "=r"((r)[3]) : "r"(a))

// mma.sync m16n8k16 fp16 (acc fp32)
__device__ __forceinline__ void mma_f16(float* c, const uint32_t* a,
                                        uint32_t b0, uint32_t b1) {
    asm volatile(
        "mma.sync.aligned.m16n8k16.row.col.f32.f16.f16.f32 "
        "{%0,%1,%2,%3}, {%4,%5,%6,%7}, {%8,%9}, {%0,%1,%2,%3};\n"
        : "+f"(c[0]), "+f"(c[1]), "+f"(c[2]), "+f"(c[3])
        : "r"(a[0]), "r"(a[1]), "r"(a[2]), "r"(a[3]), "r"(b0), "r"(b1));
}

// =====================================================================
// 2-pass fp16 GEMM body: A fp16 single [M,K], B fp16 hi/lo [N,K].
// Stage: A 10240 | Bh 10240 | Bl 10240 ; stage 30720, double-buffered.
// =====================================================================
#define GSTG 30720
#define GDSMEM (2*GSTG)

// qkv: writes Q/K -> g_qk, V -> g_v
__global__ __launch_bounds__(256, 2) void qkv_gemm() {
    extern __shared__ char smem[];
    const uint32_t sb32 = smem_u32(smem);
    const int tid = threadIdx.x, lane = tid & 31, wid = tid >> 5;
    const int warp_m = wid & 3, warp_n = wid >> 2;
    const int g = lane >> 2, ti = lane & 3;
    const uint32_t ldm_off =
        (uint32_t)((((lane >> 3) & 1) * 8 + (lane & 7)) * LDK + ((lane >> 4) * 8)) * 2;
    const int bm = blockIdx.y * 128, bn = blockIdx.x * 128;
    const int K = DIMIN;

    const __half* A0  = g_x16 + (size_t)bm * K;
    const __half* Bh0 = g_wqh + (size_t)bn * K;
    const __half* Bl0 = g_wql + (size_t)bn * K;

    float acc[2][8][4] = {};
    const int NT = K >> 5;

    auto stage = [&](uint32_t sbase, int k0) {
#pragma unroll
        for (int r = 0; r < 2; r++) {
            int sid = tid + (r << 8);
            int row = sid >> 2, seg = sid & 3;
            uint32_t so = sbase + (uint32_t)(row * (LDK * 2) + seg * 16);
            size_t oa = (size_t)row * K + k0 + seg * 8;
            cp_async16(so,          A0  + oa);
            cp_async16(so + 10240u, Bh0 + oa);
            cp_async16(so + 20480u, Bl0 + oa);
        }
    };

    stage(sb32, 0);
    CP_COMMIT();
    for (int kt = 0; kt < NT; kt++) {
        if (kt + 1 < NT) {
            stage(sb32 + ((kt + 1) & 1) * GSTG, (kt + 1) << 5);
            CP_COMMIT();
            cp_wait<1>();
        } else {
            cp_wait<0>();
        }
        __syncthreads();
        const uint32_t sb = sb32 + (kt & 1) * GSTG;
        const uint32_t bA = sb, bBh = sb + 10240, bBl = sb + 20480;
#pragma unroll
        for (int ks = 0; ks < 32; ks += 16) {
            uint32_t aF[2][4];
#pragma unroll
            for (int mt = 0; mt < 2; mt++) {
                uint32_t ro = (uint32_t)((warp_m * 32 + mt * 16) * LDK + ks) * 2 + ldm_off;
                LDM_X4(aF[mt], bA + ro);
            }
#pragma unroll
            for (int c = 0; c < 4; c++) {
                uint32_t bh[4], bl[4];
                uint32_t ro = (uint32_t)((warp_n * 64 + c * 16) * LDK + ks) * 2 + ldm_off;
                LDM_X4(bh, bBh + ro);
                LDM_X4(bl, bBl + ro);
#pragma unroll
                for (int half = 0; half < 2; half++) {
                    int nt = c * 2 + half;
#pragma unroll
                    for (int mt = 0; mt < 2; mt++) {
                        mma_f16(acc[mt][nt], aF[mt], bh[half], bh[half + 2]);
                        mma_f16(acc[mt][nt], aF[mt], bl[half], bl[half + 2]);
                    }
                }
            }
        }
        __syncthreads();
    }

    const bool isV = (bn >= 2 * HID);
#pragma unroll
    for (int mt = 0; mt < 2; mt++) {
        int r0 = bm + warp_m * 32 + mt * 16 + g;
#pragma unroll
        for (int nt = 0; nt < 8; nt++) {
            int col = bn + warp_n * 64 + nt * 8 + ti * 2;
            __half2 w0, w1;
            w0.x = __float2half(acc[mt][nt][0]);
            w0.y = __float2half(acc[mt][nt][1]);
            w1.x = __float2half(acc[mt][nt][2]);
            w1.y = __float2half(acc[mt][nt][3]);
            if (isV) {
                int cv = col - 2 * HID;
                *(__half2*)(g_v + (size_t)r0 * HID + cv)       = w0;
                *(__half2*)(g_v + (size_t)(r0 + 8) * HID + cv) = w1;
            } else {
                *(__half2*)(g_qk + (size_t)r0 * NQK + col)       = w0;
                *(__half2*)(g_qk + (size_t)(r0 + 8) * NQK + col) = w1;
            }
        }
    }
}

// =====================================================================
// scores: P = exp(scale * q.k) -> fp16. 1-pass fp16.  (round-13 proven)
// =====================================================================
#define SSTG 20480
#define SC_SMEM (2*SSTG)

__global__ __launch_bounds__(256, 2) void scores_mma() {
    extern __shared__ char smem[];
    const uint32_t sb32 = smem_u32(smem);
    const int tid = threadIdx.x, lane = tid & 31, wid = tid >> 5;
    const int warp_m = wid & 3, warp_n = wid >> 2;
    const int g = lane >> 2, ti = lane & 3;
    const uint32_t ldm_off =
        (uint32_t)((((lane >> 3) & 1) * 8 + (lane & 7)) * LDK + ((lane >> 4) * 8)) * 2;

    const int bh = blockIdx.z;
    const int b = bh >> 4, h = bh & 15;
    const int i0 = blockIdx.y * 128;
    const int j0 = blockIdx.x * 128;

    const __half* Q  = g_qk + (size_t)(b * NSEQ + i0) * NQK + h * DH;
    const __half* Kp = g_qk + (size_t)(b * NSEQ + j0) * NQK + HID + h * DH;

    auto stage2 = [&](uint32_t sbase, int k0) {
#pragma unroll
        for (int r = 0; r < 2; r++) {
            int sid = tid + (r << 8);
            int row = sid >> 2, seg = sid & 3;
            uint32_t so = sbase + (uint32_t)(row * (LDK * 2) + seg * 16);
            size_t oq = (size_t)row * NQK + k0 + seg * 8;
            cp_async16(so,          Q  + oq);
            cp_async16(so + 10240u, Kp + oq);
        }
    };

    float acc[2][8][4] = {};

    stage2(sb32,        0); CP_COMMIT();
    stage2(sb32 + SSTG, 32); CP_COMMIT();
#pragma unroll
    for (int kt = 0; kt < 2; kt++) {
        if (kt == 0) cp_wait<1>(); else cp_wait<0>();
        __syncthreads();
        const uint32_t bQ = sb32 + kt * SSTG, bK = bQ + 10240;
#pragma unroll
        for (int ks = 0; ks < 32; ks += 16) {
            uint32_t aQ[2][4];
#pragma unroll
            for (int mt = 0; mt < 2; mt++) {
                uint32_t ro = (uint32_t)((warp_m * 32 + mt * 16) * LDK + ks) * 2 + ldm_off;
                LDM_X4(aQ[mt], bQ + ro);
            }
#pragma unroll
            for (int c = 0; c < 4; c++) {
                uint32_t bk[4];
                uint32_t ro = (uint32_t)((warp_n * 64 + c * 16) * LDK + ks) * 2 + ldm_off;
                LDM_X4(bk, bK + ro);
#pragma unroll
                for (int half = 0; half < 2; half++) {
                    int nt = c * 2 + half;
#pragma unroll
                    for (int mt = 0; mt < 2; mt++)
                        mma_f16(acc[mt][nt], aQ[mt], bk[half], bk[half + 2]);
                }
            }
        }
        __syncthreads();
    }

    __half* P = g_P + (size_t)bh * NSEQ * NSEQ;
    float cs[8][2];
#pragma unroll
    for (int nt = 0; nt < 8; nt++) { cs[nt][0] = 0.f; cs[nt][1] = 0.f; }

#pragma unroll
    for (int mt = 0; mt < 2; mt++) {
        int r0 = i0 + warp_m * 32 + mt * 16 + g;
#pragma unroll
        for (int nt = 0; nt < 8; nt++) {
            int col = j0 + warp_n * 64 + nt * 8 + ti * 2;
            __half h0 = __float2half(__expf(acc[mt][nt][0] * ATT_SCALE));
            __half h1 = __float2half(__expf(acc[mt][nt][1] * ATT_SCALE));
            __half h2 = __float2half(__expf(acc[mt][nt][2] * ATT_SCALE));
            __half h3 = __float2half(__expf(acc[mt][nt][3] * ATT_SCALE));
            cs[nt][0] += __half2float(h0) + __half2float(h2);
            cs[nt][1] += __half2float(h1) + __half2float(h3);
            __half2 w0; w0.x = h0; w0.y = h1;
            __half2 w1; w1.x = h2; w1.y = h3;
            *(__half2*)(P + (size_t)r0 * NSEQ + col)       = w0;
            *(__half2*)(P + (size_t)(r0 + 8) * NSEQ + col) = w1;
        }
    }

#pragma unroll
    for (int nt = 0; nt < 8; nt++) {
#pragma unroll
        for (int e = 0; e < 2; e++) {
            float v = cs[nt][e];
            v += __shfl_xor_sync(0xFFFFFFFF, v, 4);
            v += __shfl_xor_sync(0xFFFFFFFF, v, 8);
            v += __shfl_xor_sync(0xFFFFFFFF, v, 16);
            cs[nt][e] = v;
        }
    }
    float* spart = (float*)smem;
    if (g == 0) {
#pragma unroll
        for (int nt = 0; nt < 8; nt++) {
            spart[warp_m * 128 + warp_n * 64 + nt * 8 + ti * 2]     = cs[nt][0];
            spart[warp_m * 128 + warp_n * 64 + nt * 8 + ti * 2 + 1] = cs[nt][1];
        }
    }
    __syncthreads();
    if (tid < 128) {
        float s = spart[tid] + spart[128 + tid] + spart[256 + tid] + spart[384 + tid];
        g_pcs[((size_t)bh * NITILE + blockIdx.y) * NSEQ + j0 + tid] = s;
    }
}

// =====================================================================
// rsum: rl[bh][j] = 1 / sum_itile pcs
// =====================================================================
__global__ void rsum_kernel() {
    const int bh = blockIdx.y;
    const int j = blockIdx.x * 256 + threadIdx.x;
    const float* p = g_pcs + (size_t)bh * NITILE * NSEQ + j;
    float s = 0.f;
#pragma unroll
    for (int t = 0; t < NITILE; t++) s += p[(size_t)t * NSEQ];
    g_rl[bh * NSEQ + j] = 1.0f / s;
}

// =====================================================================
// av: Y = P_fp16 @ diag(rl) V_fp16   1-pass fp16.  (round-11 proven)
// =====================================================================
__global__ __launch_bounds__(256, 2) void av_mma() {
    __shared__ __align__(16) char sm[15360]; // P 10240 | V 5120
    const uint32_t smP = smem_u32(sm);
    const uint32_t smV = smP + 10240;
    char* smVc = sm + 10240;

    const int tid = threadIdx.x, lane = tid & 31, wid = tid >> 5;
    const int g = lane >> 2, ti = lane & 3;
    const uint32_t ldm_off =
        (uint32_t)((((lane >> 3) & 1) * 8 + (lane & 7)) * LDK + ((lane >> 4) * 8)) * 2;

    const int bh = blockIdx.y;
    const int b = bh >> 4, h = bh & 15;
    const int i0 = blockIdx.x * 128;

    const __half* Pg = g_P + (size_t)bh * NSEQ * NSEQ + (size_t)i0 * NSEQ;
    const __half* Vbase = g_v + (size_t)(b * NSEQ) * HID + h * DH;
    const float* rl = g_rl + bh * NSEQ;

    const int jl = tid >> 3;            // 0..31  (V row)
    const int d0 = (tid & 7) * 8;       // V col group

    float acc[8][4] = {};

    for (int j0 = 0; j0 < NSEQ; j0 += 32) {
#pragma unroll
        for (int r = 0; r < 2; r++) {
            int sid = tid + (r << 8);
            int row = sid >> 2, seg = sid & 3;
            uint32_t so = (uint32_t)(row * (LDK * 2) + seg * 16);
            cp_async16(smP + so, Pg + (size_t)row * NSEQ + j0 + seg * 8);
        }
        CP_COMMIT();
        {
            const float inv = rl[j0 + jl];
            const __half* Vr = Vbase + (size_t)(j0 + jl) * HID + d0;
            __half2 v4[4];
            *(float4*)v4 = *(const float4*)Vr;
#pragma unroll
            for (int e = 0; e < 4; e++) {
                float lo = __half2float(v4[e].x) * inv;
                float hi = __half2float(v4[e].y) * inv;
                int off0 = ((d0 + e * 2)     * LDK + jl) * 2;
                int off1 = ((d0 + e * 2 + 1) * LDK + jl) * 2;
                *(__half*)(smVc + off0) = __float2half(lo);
                *(__half*)(smVc + off1) = __float2half(hi);
            }
        }
        cp_wait<0>();
        __syncthreads();

#pragma unroll
        for (int ks = 0; ks < 32; ks += 16) {
            uint32_t aP[4];
            uint32_t ro = (uint32_t)((wid * 16) * LDK + ks) * 2 + ldm_off;
            LDM_X4(aP, smP + ro);
#pragma unroll
            for (int c = 0; c < 4; c++) {
                uint32_t bv[4];
                uint32_t rb = (uint32_t)((c * 16) * LDK + ks) * 2 + ldm_off;
                LDM_X4(bv, smV + rb);
#pragma unroll
                for (int half = 0; half < 2; half++)
                    mma_f16(acc[c * 2 + half], aP, bv[half], bv[half + 2]);
            }
        }
        __syncthreads();
    }

    const int irow = i0 + wid * 16 + g;
#pragma unroll
    for (int nt = 0; nt < 8; nt++) {
        int d = nt * 8 + ti * 2;
        size_t o0 = (size_t)(b * NSEQ + irow) * HID + h * DH + d;
        size_t o1 = (size_t)(b * NSEQ + irow + 8) * HID + h * DH + d;
        __half2 w0; w0.x = __float2half(acc[nt][0]); w0.y = __float2half(acc[nt][1]);
        __half2 w1; w1.x = __float2half(acc[nt][2]); w1.y = __float2half(acc[nt][3]);
        *(__half2*)(g_y + o0) = w0;
        *(__half2*)(g_y + o1) = w1;
    }
}

// =====================================================================
// out-proj: out = y_fp16 @ (w_out^T fp16 hi/lo)^T + bias. 2-pass fp16.
// (round-11 proven)
// =====================================================================
__global__ __launch_bounds__(256, 2) void out_gemm(float* __restrict__ C,
                                                   const float* __restrict__ bias) {
    extern __shared__ char smem[];
    const uint32_t sb32 = smem_u32(smem);
    const int tid = threadIdx.x, lane = tid & 31, wid = tid >> 5;
    const int warp_m = wid & 3, warp_n = wid >> 2;
    const int g = lane >> 2, ti = lane & 3;
    const uint32_t ldm_off =
        (uint32_t)((((lane >> 3) & 1) * 8 + (lane & 7)) * LDK + ((lane >> 4) * 8)) * 2;
    const int bm = blockIdx.y * 128, bn = blockIdx.x * 128;
    const int K = HID, N = DIMIN;

    const __half* A0  = g_y   + (size_t)bm * K;
    const __half* Bh0 = g_woh + (size_t)bn * K;
    const __half* Bl0 = g_wol + (size_t)bn * K;

    float acc[2][8][4] = {};
    const int NT = K >> 5;

    auto stage = [&](uint32_t sbase, int k0) {
#pragma unroll
        for (int r = 0; r < 2; r++) {
            int sid = tid + (r << 8);
            int row = sid >> 2, seg = sid & 3;
            uint32_t so = sbase + (uint32_t)(row * (LDK * 2) + seg * 16);
            size_t oa = (size_t)row * K + k0 + seg * 8;
            cp_async16(so,          A0  + oa);
            cp_async16(so + 10240u, Bh0 + oa);
            cp_async16(so + 20480u, Bl0 + oa);
        }
    };

    stage(sb32, 0);
    CP_COMMIT();
    for (int kt = 0; kt < NT; kt++) {
        if (kt + 1 < NT) {
            stage(sb32 + ((kt + 1) & 1) * GSTG, (kt + 1) << 5);
            CP_COMMIT();
            cp_wait<1>();
        } else {
            cp_wait<0>();
        }
        __syncthreads();
        const uint32_t sb = sb32 + (kt & 1) * GSTG;
        const uint32_t bA = sb, bBh = sb + 10240, bBl = sb + 20480;
#pragma unroll
        for (int ks = 0; ks < 32; ks += 16) {
            uint32_t aF[2][4];
#pragma unroll
            for (int mt = 0; mt < 2; mt++) {
                uint32_t ro = (uint32_t)((warp_m * 32 + mt * 16) * LDK + ks) * 2 + ldm_off;
                LDM_X4(aF[mt], bA + ro);
            }
#pragma unroll
            for (int c = 0; c < 4; c++) {
                uint32_t bh[4], bl[4];
                uint32_t ro = (uint32_t)((warp_n * 64 + c * 16) * LDK + ks) * 2 + ldm_off;
                LDM_X4(bh, bBh + ro);
                LDM_X4(bl, bBl + ro);
#pragma unroll
                for (int half = 0; half < 2; half++) {
                    int nt = c * 2 + half;
#pragma unroll
                    for (int mt = 0; mt < 2; mt++) {
                        mma_f16(acc[mt][nt], aF[mt], bh[half], bh[half + 2]);
                        mma_f16(acc[mt][nt], aF[mt], bl[half], bl[half + 2]);
                    }
                }
            }
        }
        __syncthreads();
    }

#pragma unroll
    for (int mt = 0; mt < 2; mt++) {
        int r0 = bm + warp_m * 32 + mt * 16 + g;
#pragma unroll
        for (int nt = 0; nt < 8; nt++) {
            int col = bn + warp_n * 64 + nt * 8 + ti * 2;
            float2 bb = *(const float2*)(bias + col);
            *(float2*)(C + (size_t)r0 * N + col) =
                make_float2(acc[mt][nt][0] + bb.x, acc[mt][nt][1] + bb.y);
            *(float2*)(C + (size_t)(r0 + 8) * N + col) =
                make_float2(acc[mt][nt][2] + bb.x, acc[mt][nt][3] + bb.y);
        }
    }
}

// =====================================================================
// convert fp32 -> fp16 (elementwise)
// =====================================================================
__global__ void tofp16_kernel(const float* __restrict__ in,
                              __half* __restrict__ out, size_t n4) {
    size_t i = (size_t)blockIdx.x * blockDim.x + threadIdx.x;
    if (i >= n4) return;
    float4 v = ((const float4*)in)[i];
    __half2 a, b;
    a.x = __float2half(v.x); a.y = __float2half(v.y);
    b.x = __float2half(v.z); b.y = __float2half(v.w);
    ((__half2*)out)[i * 2 + 0] = a;
    ((__half2*)out)[i * 2 + 1] = b;
}

// transpose + split to fp16 hi/lo: w[K,N] fp32 -> th/tl [N,K]
__global__ void transpose_split_f16(const float* __restrict__ w,
                                    __half* __restrict__ th,
                                    __half* __restrict__ tl,
                                    int K, int N) {
    __shared__ float tile[32][33];
    const int k0 = blockIdx.y * 32;
    const int n0 = blockIdx.x * 32;
    const int tx = threadIdx.x, ty = threadIdx.y;   // (32,8)
#pragma unroll
    for (int r = 0; r < 4; r++)
        tile[ty + 8 * r][tx] = w[(size_t)(k0 + ty + 8 * r) * N + n0 + tx];
    __syncthreads();
#pragma unroll
    for (int r = 0; r < 4; r++) {
        const int n = n0 + ty + 8 * r;
        const int k = k0 + tx;
        float v = tile[tx][ty + 8 * r];
        __half hh = __float2half(v);
        th[(size_t)n * K + k] = hh;
        tl[(size_t)n * K + k] = __float2half(v - __half2float(hh));
    }
}

// ---------------------------------------------------------------------
extern "C" void kernel_launch(void* const* d_in, const int* in_sizes, int n_in,
                              void* d_out, int out_size) {
    const float* x     = (const float*)d_in[0];
    const float* w_qkv = (const float*)d_in[1];
    const float* w_out = (const float*)d_in[2];
    const float* b_out = (const float*)d_in[3];
    float* out = (float*)d_out;

    cudaFuncSetAttribute(qkv_gemm,
                         cudaFuncAttributeMaxDynamicSharedMemorySize, GDSMEM);
    cudaFuncSetAttribute(scores_mma,
                         cudaFuncAttributeMaxDynamicSharedMemorySize, SC_SMEM);
    cudaFuncSetAttribute(out_gemm,
                         cudaFuncAttributeMaxDynamicSharedMemorySize, GDSMEM);

    void *p_x16, *p_wqh, *p_wql, *p_woh, *p_wol;
    cudaGetSymbolAddress(&p_x16, g_x16);
    cudaGetSymbolAddress(&p_wqh, g_wqh);
    cudaGetSymbolAddress(&p_wql, g_wql);
    cudaGetSymbolAddress(&p_woh, g_woh);
    cudaGetSymbolAddress(&p_wol, g_wol);

    // 0a. x -> fp16
    {
        size_t n4 = (size_t)ROWS * DIMIN / 4;
        tofp16_kernel<<<(unsigned)((n4 + 255) / 256), 256>>>(
            x, (__half*)p_x16, n4);
    }
    // 0b. transpose+split w_qkv -> fp16 hi/lo [N,K]
    transpose_split_f16<<<dim3(QKV_COLS / 32, DIMIN / 32), dim3(32, 8)>>>(
        w_qkv, (__half*)p_wqh, (__half*)p_wql, DIMIN, QKV_COLS);
    // 0c. transpose+split w_out -> fp16 hi/lo [N,K]
    transpose_split_f16<<<dim3(HID / 32, DIMIN / 32), dim3(32, 8)>>>(
        w_out, (__half*)p_woh, (__half*)p_wol, DIMIN, HID);

    // 1. QKV projection (2-pass fp16): Q/K -> g_qk, V -> g_v
    qkv_gemm<<<dim3(QKV_COLS / 128, ROWS / 128), 256, GDSMEM>>>();

    // 2. P = exp(scale * Q K^T) (fp16, 1-pass) + partial column sums
    scores_mma<<<dim3(NSEQ / 128, NSEQ / 128, BH), 256, SC_SMEM>>>();

    // 3. rl = 1 / column sums
    rsum_kernel<<<dim3(NSEQ / 256, BH), 256>>>();

    // 4. Y = P diag(rl) V  -> y fp16
    av_mma<<<dim3(NSEQ / 128, BH), 256>>>();

    // 5. out = Y @ w_out + b_out (2-pass fp16)
    out_gemm<<<dim3(HID / 128, ROWS / 128), 256, GDSMEM>>>(out, b_out);
}

// round 16
// speedup vs baseline: 2.2398x; 1.0174x over previous
#include <cuda_runtime.h>
#include <cuda_fp16.h>
#include <math.h>
#include <stdint.h>

#define HEADS    16
#define DH       64
#define NSEQ     2048
#define BATCH    4
#define DIMIN    1024
#define HID      1024
#define ROWS     (BATCH*NSEQ)     // 8192
#define QKV_COLS (3*HID)          // 3072
#define BH       (BATCH*HEADS)    // 64
#define ATT_SCALE 0.125f
#define LDK      40               // padded k-stride (2B elems)  [proven layout]
#define NITILE   (NSEQ/128)       // 16
#define NQK      (2*HID)          // 2048

// ---------------- static scratch ----------------
__device__ float g_rl[BH * NSEQ];
__device__ float g_pcs[(size_t)BH * NITILE * NSEQ];
__device__ __half g_P [(size_t)BH * NSEQ * NSEQ];
__device__ __half g_qk[(size_t)ROWS * NQK];
__device__ __half g_v [(size_t)ROWS * HID];
__device__ __half g_y [(size_t)ROWS * HID];
__device__ __half g_x16[(size_t)ROWS * DIMIN];
__device__ __half g_wqh[(size_t)QKV_COLS * DIMIN];
__device__ __half g_wql[(size_t)QKV_COLS * DIMIN];
__device__ __half g_woh[(size_t)DIMIN * HID];
__device__ __half g_wol[(size_t)DIMIN * HID];

// ---------------- helpers ----------------
__device__ __forceinline__ uint32_t smem_u32(const void* p) {
    uint32_t a;
    asm("{ .reg .u64 t; cvta.to.shared.u64 t, %1; cvt.u32.u64 %0, t; }"
        : "=r"(a) : "l"(p));
    return a;
}
__device__ __forceinline__ void cp_async16(uint32_t s, const void* g) {
    asm volatile("cp.async.cg.shared.global [%0], [%1], 16;" :: "r"(s), "l"(g));
}
#define CP_COMMIT() asm volatile("cp.async.commit_group;" ::: "memory")
template <int N>
__device__ __forceinline__ void cp_wait() {
    asm volatile("cp.async.wait_group %0;" :: "n"(N) : "memory");
}
#define LDM_X4(r, a)                                                        \
    asm volatile("ldmatrix.sync.aligned.m8n8.x4.shared.b16 {%0,%1,%2,%3}, [%4];" \
        : "=r"((r)[0]), "=r"((r)[1]), "=r"((r)[2]), "=r"((r)[3]) : "r"(a))

__device__ __forceinline__ void mma_f16(float* c, const uint32_t* a,
                                        uint32_t b0, uint32_t b1) {
    asm volatile(
        "mma.sync.aligned.m16n8k16.row.col.f32.f16.f16.f32 "
        "{%0,%1,%2,%3}, {%4,%5,%6,%7}, {%8,%9}, {%0,%1,%2,%3};\n"
        : "+f"(c[0]), "+f"(c[1]), "+f"(c[2]), "+f"(c[3])
        : "r"(a[0]), "r"(a[1]), "r"(a[2]), "r"(a[3]), "r"(b0), "r"(b1));
}

// =====================================================================
// 2-pass fp16 GEMM: A fp16 [M,K], B fp16 hi/lo [N,K].
// Stage: A 10240 | Bh 10240 | Bl 10240 = 30720; THREE stages, 1 barrier/chunk.
// =====================================================================
#define GSTG 30720
#define GDSMEM (3*GSTG)    // 92160

// qkv: writes Q/K -> g_qk, V -> g_v
__global__ __launch_bounds__(256, 2) void qkv_gemm() {
    extern __shared__ char smem[];
    const uint32_t sb32 = smem_u32(smem);
    const int tid = threadIdx.x, lane = tid & 31, wid = tid >> 5;
    const int warp_m = wid & 3, warp_n = wid >> 2;
    const int g = lane >> 2, ti = lane & 3;
    const uint32_t ldm_off =
        (uint32_t)((((lane >> 3) & 1) * 8 + (lane & 7)) * LDK + ((lane >> 4) * 8)) * 2;
    const int bm = blockIdx.y * 128, bn = blockIdx.x * 128;
    const int K = DIMIN;

    const __half* A0  = g_x16 + (size_t)bm * K;
    const __half* Bh0 = g_wqh + (size_t)bn * K;
    const __half* Bl0 = g_wql + (size_t)bn * K;

    float acc[2][8][4] = {};
    const int NT = K >> 5;

    auto stage = [&](uint32_t sbase, int k0) {
#pragma unroll
        for (int r = 0; r < 2; r++) {
            int sid = tid + (r << 8);
            int row = sid >> 2, seg = sid & 3;
            uint32_t so = sbase + (uint32_t)(row * (LDK * 2) + seg * 16);
            size_t oa = (size_t)row * K + k0 + seg * 8;
            cp_async16(so,          A0  + oa);
            cp_async16(so + 10240u, Bh0 + oa);
            cp_async16(so + 20480u, Bl0 + oa);
        }
    };

    stage(sb32,        0);  CP_COMMIT();
    stage(sb32 + GSTG, 32); CP_COMMIT();

    for (int kt = 0; kt < NT; kt++) {
        cp_wait<1>();
        __syncthreads();                 // data(kt) visible + stage (kt+2)%3 free
        if (kt + 2 < NT) stage(sb32 + ((kt + 2) % 3) * GSTG, (kt + 2) << 5);
        CP_COMMIT();                     // unconditional: keeps group count exact

        const uint32_t sb = sb32 + (kt % 3) * GSTG;
        const uint32_t bA = sb, bBh = sb + 10240, bBl = sb + 20480;
#pragma unroll
        for (int ks = 0; ks < 32; ks += 16) {
            uint32_t aF[2][4];
#pragma unroll
            for (int mt = 0; mt < 2; mt++) {
                uint32_t ro = (uint32_t)((warp_m * 32 + mt * 16) * LDK + ks) * 2 + ldm_off;
                LDM_X4(aF[mt], bA + ro);
            }
#pragma unroll
            for (int c = 0; c < 4; c++) {
                uint32_t bh[4], bl[4];
                uint32_t ro = (uint32_t)((warp_n * 64 + c * 16) * LDK + ks) * 2 + ldm_off;
                LDM_X4(bh, bBh + ro);
                LDM_X4(bl, bBl + ro);
#pragma unroll
                for (int half = 0; half < 2; half++) {
                    int nt = c * 2 + half;
#pragma unroll
                    for (int mt = 0; mt < 2; mt++) {
                        mma_f16(acc[mt][nt], aF[mt], bh[half], bh[half + 2]);
                        mma_f16(acc[mt][nt], aF[mt], bl[half], bl[half + 2]);
                    }
                }
            }
        }
    }

    const bool isV = (bn >= 2 * HID);
#pragma unroll
    for (int mt = 0; mt < 2; mt++) {
        int r0 = bm + warp_m * 32 + mt * 16 + g;
#pragma unroll
        for (int nt = 0; nt < 8; nt++) {
            int col = bn + warp_n * 64 + nt * 8 + ti * 2;
            __half2 w0, w1;
            w0.x = __float2half(acc[mt][nt][0]);
            w0.y = __float2half(acc[mt][nt][1]);
            w1.x = __float2half(acc[mt][nt][2]);
            w1.y = __float2half(acc[mt][nt][3]);
            if (isV) {
                int cv = col - 2 * HID;
                *(__half2*)(g_v + (size_t)r0 * HID + cv)       = w0;
                *(__half2*)(g_v + (size_t)(r0 + 8) * HID + cv) = w1;
            } else {
                *(__half2*)(g_qk + (size_t)r0 * NQK + col)       = w0;
                *(__half2*)(g_qk + (size_t)(r0 + 8) * NQK + col) = w1;
            }
        }
    }
}

// =====================================================================
// scores: P = exp(scale * q.k) -> fp16, 1-pass fp16. Both K-chunks loaded
// up front, single wait+sync.
// =====================================================================
#define SSTG 20480
#define SC_SMEM (2*SSTG)

__global__ __launch_bounds__(256, 2) void scores_mma() {
    extern __shared__ char smem[];
    const uint32_t sb32 = smem_u32(smem);
    const int tid = threadIdx.x, lane = tid & 31, wid = tid >> 5;
    const int warp_m = wid & 3, warp_n = wid >> 2;
    const int g = lane >> 2, ti = lane & 3;
    const uint32_t ldm_off =
        (uint32_t)((((lane >> 3) & 1) * 8 + (lane & 7)) * LDK + ((lane >> 4) * 8)) * 2;

    const int bh = blockIdx.z;
    const int b = bh >> 4, h = bh & 15;
    const int i0 = blockIdx.y * 128;
    const int j0 = blockIdx.x * 128;

    const __half* Q  = g_qk + (size_t)(b * NSEQ + i0) * NQK + h * DH;
    const __half* Kp = g_qk + (size_t)(b * NSEQ + j0) * NQK + HID + h * DH;

    auto stage2 = [&](uint32_t sbase, int k0) {
#pragma unroll
        for (int r = 0; r < 2; r++) {
            int sid = tid + (r << 8);
            int row = sid >> 2, seg = sid & 3;
            uint32_t so = sbase + (uint32_t)(row * (LDK * 2) + seg * 16);
            size_t oq = (size_t)row * NQK + k0 + seg * 8;
            cp_async16(so,          Q  + oq);
            cp_async16(so + 10240u, Kp + oq);
        }
    };

    float acc[2][8][4] = {};

    stage2(sb32,        0);
    stage2(sb32 + SSTG, 32);
    CP_COMMIT();
    cp_wait<0>();
    __syncthreads();

#pragma unroll
    for (int kt = 0; kt < 2; kt++) {
        const uint32_t bQ = sb32 + kt * SSTG, bK = bQ + 10240;
#pragma unroll
        for (int ks = 0; ks < 32; ks += 16) {
            uint32_t aQ[2][4];
#pragma unroll
            for (int mt = 0; mt < 2; mt++) {
                uint32_t ro = (uint32_t)((warp_m * 32 + mt * 16) * LDK + ks) * 2 + ldm_off;
                LDM_X4(aQ[mt], bQ + ro);
            }
#pragma unroll
            for (int c = 0; c < 4; c++) {
                uint32_t bk[4];
                uint32_t ro = (uint32_t)((warp_n * 64 + c * 16) * LDK + ks) * 2 + ldm_off;
                LDM_X4(bk, bK + ro);
#pragma unroll
                for (int half = 0; half < 2; half++) {
                    int nt = c * 2 + half;
#pragma unroll
                    for (int mt = 0; mt < 2; mt++)
                        mma_f16(acc[mt][nt], aQ[mt], bk[half], bk[half + 2]);
                }
            }
        }
    }
    __syncthreads();                     // before spart reuse of stage smem

    __half* P = g_P + (size_t)bh * NSEQ * NSEQ;
    float cs[8][2];
#pragma unroll
    for (int nt = 0; nt < 8; nt++) { cs[nt][0] = 0.f; cs[nt][1] = 0.f; }

#pragma unroll
    for (int mt = 0; mt < 2; mt++) {
        int r0 = i0 + warp_m * 32 + mt * 16 + g;
#pragma unroll
        for (int nt = 0; nt < 8; nt++) {
            int col = j0 + warp_n * 64 + nt * 8 + ti * 2;
            __half h0 = __float2half(__expf(acc[mt][nt][0] * ATT_SCALE));
            __half h1 = __float2half(__expf(acc[mt][nt][1] * ATT_SCALE));
            __half h2 = __float2half(__expf(acc[mt][nt][2] * ATT_SCALE));
            __half h3 = __float2half(__expf(acc[mt][nt][3] * ATT_SCALE));
            cs[nt][0] += __half2float(h0) + __half2float(h2);
            cs[nt][1] += __half2float(h1) + __half2float(h3);
            __half2 w0; w0.x = h0; w0.y = h1;
            __half2 w1; w1.x = h2; w1.y = h3;
            *(__half2*)(P + (size_t)r0 * NSEQ + col)       = w0;
            *(__half2*)(P + (size_t)(r0 + 8) * NSEQ + col) = w1;
        }
    }

#pragma unroll
    for (int nt = 0; nt < 8; nt++) {
#pragma unroll
        for (int e = 0; e < 2; e++) {
            float v = cs[nt][e];
            v += __shfl_xor_sync(0xFFFFFFFF, v, 4);
            v += __shfl_xor_sync(0xFFFFFFFF, v, 8);
            v += __shfl_xor_sync(0xFFFFFFFF, v, 16);
            cs[nt][e] = v;
        }
    }
    float* spart = (float*)smem;
    if (g == 0) {
#pragma unroll
        for (int nt = 0; nt < 8; nt++) {
            spart[warp_m * 128 + warp_n * 64 + nt * 8 + ti * 2]     = cs[nt][0];
            spart[warp_m * 128 + warp_n * 64 + nt * 8 + ti * 2 + 1] = cs[nt][1];
        }
    }
    __syncthreads();
    if (tid < 128) {
        float s = spart[tid] + spart[128 + tid] + spart[256 + tid] + spart[384 + tid];
        g_pcs[((size_t)bh * NITILE + blockIdx.y) * NSEQ + j0 + tid] = s;
    }
}

// =====================================================================
// rsum: rl[bh][j] = 1 / sum_itile pcs
// =====================================================================
__global__ void rsum_kernel() {
    const int bh = blockIdx.y;
    const int j = blockIdx.x * 256 + threadIdx.x;
    const float* p = g_pcs + (size_t)bh * NITILE * NSEQ + j;
    float s = 0.f;
#pragma unroll
    for (int t = 0; t < NITILE; t++) s += p[(size_t)t * NSEQ];
    g_rl[bh * NSEQ + j] = 1.0f / s;
}

// =====================================================================
// av: Y = P_fp16 @ diag(rl) V_fp16, 1-pass fp16.
// 64-j iteration (two 32-j sub-buffers): barriers halved vs round-14.
// smem: P0 10240 | P1 10240 | V0 5120 | V1 5120 = 30720 static.
// =====================================================================
__global__ __launch_bounds__(256, 2) void av_mma() {
    __shared__ __align__(16) char sm[30720];
    const uint32_t smP = smem_u32(sm);
    const uint32_t smV = smP + 20480;
    char* smVc = sm + 20480;

    const int tid = threadIdx.x, lane = tid & 31, wid = tid >> 5;
    const int g = lane >> 2, ti = lane & 3;
    const uint32_t ldm_off =
        (uint32_t)((((lane >> 3) & 1) * 8 + (lane & 7)) * LDK + ((lane >> 4) * 8)) * 2;

    const int bh = blockIdx.y;
    const int b = bh >> 4, h = bh & 15;
    const int i0 = blockIdx.x * 128;

    const __half* Pg = g_P + (size_t)bh * NSEQ * NSEQ + (size_t)i0 * NSEQ;
    const __half* Vbase = g_v + (size_t)(b * NSEQ) * HID + h * DH;
    const float* rl = g_rl + bh * NSEQ;

    const int jl = tid >> 3;            // 0..31  (V row within sub-tile)
    const int d0 = (tid & 7) * 8;       // V col group

    float acc[8][4] = {};

    for (int j0 = 0; j0 < NSEQ; j0 += 64) {
        // P: both 32-j sub-tiles
#pragma unroll
        for (int hf = 0; hf < 2; hf++) {
#pragma unroll
            for (int r = 0; r < 2; r++) {
                int sid = tid + (r << 8);
                int row = sid >> 2, seg = sid & 3;
                uint32_t so = (uint32_t)(hf * 10240 + row * (LDK * 2) + seg * 16);
                cp_async16(smP + so,
                           Pg + (size_t)row * NSEQ + j0 + hf * 32 + seg * 8);
            }
        }
        CP_COMMIT();
        // V: both sub-tiles, rl folded in, transposed [d][j]
#pragma unroll
        for (int hf = 0; hf < 2; hf++) {
            const float inv = rl[j0 + hf * 32 + jl];
            const __half* Vr = Vbase + (size_t)(j0 + hf * 32 + jl) * HID + d0;
            __half2 v4[4];
            *(float4*)v4 = *(const float4*)Vr;
            char* vb = smVc + hf * 5120;
#pragma unroll
            for (int e = 0; e < 4; e++) {
                float lo = __half2float(v4[e].x) * inv;
                float hi = __half2float(v4[e].y) * inv;
                int off0 = ((d0 + e * 2)     * LDK + jl) * 2;
                int off1 = ((d0 + e * 2 + 1) * LDK + jl) * 2;
                *(__half*)(vb + off0) = __float2half(lo);
                *(__half*)(vb + off1) = __float2half(hi);
            }
        }
        cp_wait<0>();
        __syncthreads();

#pragma unroll
        for (int hf = 0; hf < 2; hf++) {
            const uint32_t Pst = smP + hf * 10240;
            const uint32_t Vst = smV + hf * 5120;
#pragma unroll
            for (int ks = 0; ks < 32; ks += 16) {
                uint32_t aP[4];
                uint32_t ro = (uint32_t)((wid * 16) * LDK + ks) * 2 + ldm_off;
                LDM_X4(aP, Pst + ro);
#pragma unroll
                for (int c = 0; c < 4; c++) {
                    uint32_t bv[4];
                    uint32_t rb = (uint32_t)((c * 16) * LDK + ks) * 2 + ldm_off;
                    LDM_X4(bv, Vst + rb);
#pragma unroll
                    for (int half = 0; half < 2; half++)
                        mma_f16(acc[c * 2 + half], aP, bv[half], bv[half + 2]);
                }
            }
        }
        __syncthreads();
    }

    const int irow = i0 + wid * 16 + g;
#pragma unroll
    for (int nt = 0; nt < 8; nt++) {
        int d = nt * 8 + ti * 2;
        size_t o0 = (size_t)(b * NSEQ + irow) * HID + h * DH + d;
        size_t o1 = (size_t)(b * NSEQ + irow + 8) * HID + h * DH + d;
        __half2 w0; w0.x = __float2half(acc[nt][0]); w0.y = __float2half(acc[nt][1]);
        __half2 w1; w1.x = __float2half(acc[nt][2]); w1.y = __float2half(acc[nt][3]);
        *(__half2*)(g_y + o0) = w0;
        *(__half2*)(g_y + o1) = w1;
    }
}

// =====================================================================
// out-proj: out = y_fp16 @ (w_out^T fp16 hi/lo)^T + bias. 2-pass fp16,
// 3-stage, 1 barrier/chunk.
// =====================================================================
__global__ __launch_bounds__(256, 2) void out_gemm(float* __restrict__ C,
                                                   const float* __restrict__ bias) {
    extern __shared__ char smem[];
    const uint32_t sb32 = smem_u32(smem);
    const int tid = threadIdx.x, lane = tid & 31, wid = tid >> 5;
    const int warp_m = wid & 3, warp_n = wid >> 2;
    const int g = lane >> 2, ti = lane & 3;
    const uint32_t ldm_off =
        (uint32_t)((((lane >> 3) & 1) * 8 + (lane & 7)) * LDK + ((lane >> 4) * 8)) * 2;
    const int bm = blockIdx.y * 128, bn = blockIdx.x * 128;
    const int K = HID, N = DIMIN;

    const __half* A0  = g_y   + (size_t)bm * K;
    const __half* Bh0 = g_woh + (size_t)bn * K;
    const __half* Bl0 = g_wol + (size_t)bn * K;

    float acc[2][8][4] = {};
    const int NT = K >> 5;

    auto stage = [&](uint32_t sbase, int k0) {
#pragma unroll
        for (int r = 0; r < 2; r++) {
            int sid = tid + (r << 8);
            int row = sid >> 2, seg = sid & 3;
            uint32_t so = sbase + (uint32_t)(row * (LDK * 2) + seg * 16);
            size_t oa = (size_t)row * K + k0 + seg * 8;
            cp_async16(so,          A0  + oa);
            cp_async16(so + 10240u, Bh0 + oa);
            cp_async16(so + 20480u, Bl0 + oa);
        }
    };

    stage(sb32,        0);  CP_COMMIT();
    stage(sb32 + GSTG, 32); CP_COMMIT();

    for (int kt = 0; kt < NT; kt++) {
        cp_wait<1>();
        __syncthreads();
        if (kt + 2 < NT) stage(sb32 + ((kt + 2) % 3) * GSTG, (kt + 2) << 5);
        CP_COMMIT();

        const uint32_t sb = sb32 + (kt % 3) * GSTG;
        const uint32_t bA = sb, bBh = sb + 10240, bBl = sb + 20480;
#pragma unroll
        for (int ks = 0; ks < 32; ks += 16) {
            uint32_t aF[2][4];
#pragma unroll
            for (int mt = 0; mt < 2; mt++) {
                uint32_t ro = (uint32_t)((warp_m * 32 + mt * 16) * LDK + ks) * 2 + ldm_off;
                LDM_X4(aF[mt], bA + ro);
            }
#pragma unroll
            for (int c = 0; c < 4; c++) {
                uint32_t bh[4], bl[4];
                uint32_t ro = (uint32_t)((warp_n * 64 + c * 16) * LDK + ks) * 2 + ldm_off;
                LDM_X4(bh, bBh + ro);
                LDM_X4(bl, bBl + ro);
#pragma unroll
                for (int half = 0; half < 2; half++) {
                    int nt = c * 2 + half;
#pragma unroll
                    for (int mt = 0; mt < 2; mt++) {
                        mma_f16(acc[mt][nt], aF[mt], bh[half], bh[half + 2]);
                        mma_f16(acc[mt][nt], aF[mt], bl[half], bl[half + 2]);
                    }
                }
            }
        }
    }

#pragma unroll
    for (int mt = 0; mt < 2; mt++) {
        int r0 = bm + warp_m * 32 + mt * 16 + g;
#pragma unroll
        for (int nt = 0; nt < 8; nt++) {
            int col = bn + warp_n * 64 + nt * 8 + ti * 2;
            float2 bb = *(const float2*)(bias + col);
            *(float2*)(C + (size_t)r0 * N + col) =
                make_float2(acc[mt][nt][0] + bb.x, acc[mt][nt][1] + bb.y);
            *(float2*)(C + (size_t)(r0 + 8) * N + col) =
                make_float2(acc[mt][nt][2] + bb.x, acc[mt][nt][3] + bb.y);
        }
    }
}

// =====================================================================
// convert fp32 -> fp16 (elementwise)
// =====================================================================
__global__ void tofp16_kernel(const float* __restrict__ in,
                              __half* __restrict__ out, size_t n4) {
    size_t i = (size_t)blockIdx.x * blockDim.x + threadIdx.x;
    if (i >= n4) return;
    float4 v = ((const float4*)in)[i];
    __half2 a, b;
    a.x = __float2half(v.x); a.y = __float2half(v.y);
    b.x = __float2half(v.z); b.y = __float2half(v.w);
    ((__half2*)out)[i * 2 + 0] = a;
    ((__half2*)out)[i * 2 + 1] = b;
}

// transpose + split to fp16 hi/lo: w[K,N] fp32 -> th/tl [N,K]
__global__ void transpose_split_f16(const float* __restrict__ w,
                                    __half* __restrict__ th,
                                    __half* __restrict__ tl,
                                    int K, int N) {
    __shared__ float tile[32][33];
    const int k0 = blockIdx.y * 32;
    const int n0 = blockIdx.x * 32;
    const int tx = threadIdx.x, ty = threadIdx.y;   // (32,8)
#pragma unroll
    for (int r = 0; r < 4; r++)
        tile[ty + 8 * r][tx] = w[(size_t)(k0 + ty + 8 * r) * N + n0 + tx];
    __syncthreads();
#pragma unroll
    for (int r = 0; r < 4; r++) {
        const int n = n0 + ty + 8 * r;
        const int k = k0 + tx;
        float v = tile[tx][ty + 8 * r];
        __half hh = __float2half(v);
        th[(size_t)n * K + k] = hh;
        tl[(size_t)n * K + k] = __float2half(v - __half2float(hh));
    }
}

// ---------------------------------------------------------------------
extern "C" void kernel_launch(void* const* d_in, const int* in_sizes, int n_in,
                              void* d_out, int out_size) {
    const float* x     = (const float*)d_in[0];
    const float* w_qkv = (const float*)d_in[1];
    const float* w_out = (const float*)d_in[2];
    const float* b_out = (const float*)d_in[3];
    float* out = (float*)d_out;

    cudaFuncSetAttribute(qkv_gemm,
                         cudaFuncAttributeMaxDynamicSharedMemorySize, GDSMEM);
    cudaFuncSetAttribute(scores_mma,
                         cudaFuncAttributeMaxDynamicSharedMemorySize, SC_SMEM);
    cudaFuncSetAttribute(out_gemm,
                         cudaFuncAttributeMaxDynamicSharedMemorySize, GDSMEM);

    void *p_x16, *p_wqh, *p_wql, *p_woh, *p_wol;
    cudaGetSymbolAddress(&p_x16, g_x16);
    cudaGetSymbolAddress(&p_wqh, g_wqh);
    cudaGetSymbolAddress(&p_wql, g_wql);
    cudaGetSymbolAddress(&p_woh, g_woh);
    cudaGetSymbolAddress(&p_wol, g_wol);

    // 0a. x -> fp16
    {
        size_t n4 = (size_t)ROWS * DIMIN / 4;
        tofp16_kernel<<<(unsigned)((n4 + 255) / 256), 256>>>(
            x, (__half*)p_x16, n4);
    }
    // 0b/0c. transpose+split weights -> fp16 hi/lo [N,K]
    transpose_split_f16<<<dim3(QKV_COLS / 32, DIMIN / 32), dim3(32, 8)>>>(
        w_qkv, (__half*)p_wqh, (__half*)p_wql, DIMIN, QKV_COLS);
    transpose_split_f16<<<dim3(HID / 32, DIMIN / 32), dim3(32, 8)>>>(
        w_out, (__half*)p_woh, (__half*)p_wol, DIMIN, HID);

    // 1. QKV projection (2-pass fp16, 3-stage)
    qkv_gemm<<<dim3(QKV_COLS / 128, ROWS / 128), 256, GDSMEM>>>();

    // 2. P = exp(scale * Q K^T) (fp16, 1-pass) + partial column sums
    scores_mma<<<dim3(NSEQ / 128, NSEQ / 128, BH), 256, SC_SMEM>>>();

    // 3. rl = 1 / column sums
    rsum_kernel<<<dim3(NSEQ / 256, BH), 256>>>();

    // 4. Y = P diag(rl) V  -> y fp16  (64-j iterations)
    av_mma<<<dim3(NSEQ / 128, BH), 256>>>();

    // 5. out = Y @ w_out + b_out (2-pass fp16, 3-stage)
    out_gemm<<<dim3(HID / 128, ROWS / 128), 256, GDSMEM>>>(out, b_out);
}

// round 17
// speedup vs baseline: 2.2655x; 1.0115x over previous
#include <cuda_runtime.h>
#include <cuda_fp16.h>
#include <math.h>
#include <stdint.h>

#define HEADS    16
#define DH       64
#define NSEQ     2048
#define BATCH    4
#define DIMIN    1024
#define HID      1024
#define ROWS     (BATCH*NSEQ)     // 8192
#define QKV_COLS (3*HID)          // 3072
#define BH       (BATCH*HEADS)    // 64
#define ATT_SCALE 0.125f
#define LDK      40               // padded k-stride (2B elems)  [proven layout]
#define NITILE   (NSEQ/128)       // 16
#define NQK      (2*HID)          // 2048

// ---------------- static scratch ----------------
__device__ float g_rl[BH * NSEQ];
__device__ float g_pcs[(size_t)BH * NITILE * NSEQ];
__device__ __half g_P [(size_t)BH * NSEQ * NSEQ];
__device__ __half g_qk[(size_t)ROWS * NQK];
__device__ __half g_v [(size_t)ROWS * HID];
__device__ __half g_y [(size_t)ROWS * HID];
__device__ __half g_x16[(size_t)ROWS * DIMIN];
__device__ __half g_wqh[(size_t)QKV_COLS * DIMIN];
__device__ __half g_wql[(size_t)QKV_COLS * DIMIN];
__device__ __half g_woh[(size_t)DIMIN * HID];
__device__ __half g_wol[(size_t)DIMIN * HID];

// ---------------- helpers ----------------
__device__ __forceinline__ uint32_t smem_u32(const void* p) {
    uint32_t a;
    asm("{ .reg .u64 t; cvta.to.shared.u64 t, %1; cvt.u32.u64 %0, t; }"
        : "=r"(a) : "l"(p));
    return a;
}
__device__ __forceinline__ void cp_async16(uint32_t s, const void* g) {
    asm volatile("cp.async.cg.shared.global [%0], [%1], 16;" :: "r"(s), "l"(g));
}
#define CP_COMMIT() asm volatile("cp.async.commit_group;" ::: "memory")
template <int N>
__device__ __forceinline__ void cp_wait() {
    asm volatile("cp.async.wait_group %0;" :: "n"(N) : "memory");
}
#define LDM_X4(r, a)                                                        \
    asm volatile("ldmatrix.sync.aligned.m8n8.x4.shared.b16 {%0,%1,%2,%3}, [%4];" \
        : "=r"((r)[0]), "=r"((r)[1]), "=r"((r)[2]), "=r"((r)[3]) : "r"(a))

__device__ __forceinline__ void mma_f16(float* c, const uint32_t* a,
                                        uint32_t b0, uint32_t b1) {
    asm volatile(
        "mma.sync.aligned.m16n8k16.row.col.f32.f16.f16.f32 "
        "{%0,%1,%2,%3}, {%4,%5,%6,%7}, {%8,%9}, {%0,%1,%2,%3};\n"
        : "+f"(c[0]), "+f"(c[1]), "+f"(c[2]), "+f"(c[3])
        : "r"(a[0]), "r"(a[1]), "r"(a[2]), "r"(a[3]), "r"(b0), "r"(b1));
}

// =====================================================================
// 2-pass fp16 GEMM: A fp16 [M,K], B fp16 hi/lo [N,K].
// Stage: A 10240 | Bh 10240 | Bl 10240 = 30720.
// qkv: 2-stage double-buffer (round-14 measured-best).
// =====================================================================
#define GSTG 30720
#define QDSMEM (2*GSTG)    // 61440 (qkv)
#define ODSMEM (3*GSTG)    // 92160 (out, 3-stage, round-16 measured-best)

// qkv: writes Q/K -> g_qk, V -> g_v
__global__ __launch_bounds__(256, 2) void qkv_gemm() {
    extern __shared__ char smem[];
    const uint32_t sb32 = smem_u32(smem);
    const int tid = threadIdx.x, lane = tid & 31, wid = tid >> 5;
    const int warp_m = wid & 3, warp_n = wid >> 2;
    const int g = lane >> 2, ti = lane & 3;
    const uint32_t ldm_off =
        (uint32_t)((((lane >> 3) & 1) * 8 + (lane & 7)) * LDK + ((lane >> 4) * 8)) * 2;
    const int bm = blockIdx.y * 128, bn = blockIdx.x * 128;
    const int K = DIMIN;

    const __half* A0  = g_x16 + (size_t)bm * K;
    const __half* Bh0 = g_wqh + (size_t)bn * K;
    const __half* Bl0 = g_wql + (size_t)bn * K;

    float acc[2][8][4] = {};
    const int NT = K >> 5;

    auto stage = [&](uint32_t sbase, int k0) {
#pragma unroll
        for (int r = 0; r < 2; r++) {
            int sid = tid + (r << 8);
            int row = sid >> 2, seg = sid & 3;
            uint32_t so = sbase + (uint32_t)(row * (LDK * 2) + seg * 16);
            size_t oa = (size_t)row * K + k0 + seg * 8;
            cp_async16(so,          A0  + oa);
            cp_async16(so + 10240u, Bh0 + oa);
            cp_async16(so + 20480u, Bl0 + oa);
        }
    };

    stage(sb32, 0);
    CP_COMMIT();
    for (int kt = 0; kt < NT; kt++) {
        if (kt + 1 < NT) {
            stage(sb32 + ((kt + 1) & 1) * GSTG, (kt + 1) << 5);
            CP_COMMIT();
            cp_wait<1>();
        } else {
            cp_wait<0>();
        }
        __syncthreads();
        const uint32_t sb = sb32 + (kt & 1) * GSTG;
        const uint32_t bA = sb, bBh = sb + 10240, bBl = sb + 20480;
#pragma unroll
        for (int ks = 0; ks < 32; ks += 16) {
            uint32_t aF[2][4];
#pragma unroll
            for (int mt = 0; mt < 2; mt++) {
                uint32_t ro = (uint32_t)((warp_m * 32 + mt * 16) * LDK + ks) * 2 + ldm_off;
                LDM_X4(aF[mt], bA + ro);
            }
#pragma unroll
            for (int c = 0; c < 4; c++) {
                uint32_t bh[4], bl[4];
                uint32_t ro = (uint32_t)((warp_n * 64 + c * 16) * LDK + ks) * 2 + ldm_off;
                LDM_X4(bh, bBh + ro);
                LDM_X4(bl, bBl + ro);
#pragma unroll
                for (int half = 0; half < 2; half++) {
                    int nt = c * 2 + half;
#pragma unroll
                    for (int mt = 0; mt < 2; mt++) {
                        mma_f16(acc[mt][nt], aF[mt], bh[half], bh[half + 2]);
                        mma_f16(acc[mt][nt], aF[mt], bl[half], bl[half + 2]);
                    }
                }
            }
        }
        __syncthreads();
    }

    const bool isV = (bn >= 2 * HID);
#pragma unroll
    for (int mt = 0; mt < 2; mt++) {
        int r0 = bm + warp_m * 32 + mt * 16 + g;
#pragma unroll
        for (int nt = 0; nt < 8; nt++) {
            int col = bn + warp_n * 64 + nt * 8 + ti * 2;
            __half2 w0, w1;
            w0.x = __float2half(acc[mt][nt][0]);
            w0.y = __float2half(acc[mt][nt][1]);
            w1.x = __float2half(acc[mt][nt][2]);
            w1.y = __float2half(acc[mt][nt][3]);
            if (isV) {
                int cv = col - 2 * HID;
                *(__half2*)(g_v + (size_t)r0 * HID + cv)       = w0;
                *(__half2*)(g_v + (size_t)(r0 + 8) * HID + cv) = w1;
            } else {
                *(__half2*)(g_qk + (size_t)r0 * NQK + col)       = w0;
                *(__half2*)(g_qk + (size_t)(r0 + 8) * NQK + col) = w1;
            }
        }
    }
}

// =====================================================================
// scores: P = exp(scale * q.k) -> fp16, 1-pass fp16. Both K-chunks loaded
// up front, single wait+sync.  (round-16 measured-best)
// =====================================================================
#define SSTG 20480
#define SC_SMEM (2*SSTG)

__global__ __launch_bounds__(256, 2) void scores_mma() {
    extern __shared__ char smem[];
    const uint32_t sb32 = smem_u32(smem);
    const int tid = threadIdx.x, lane = tid & 31, wid = tid >> 5;
    const int warp_m = wid & 3, warp_n = wid >> 2;
    const int g = lane >> 2, ti = lane & 3;
    const uint32_t ldm_off =
        (uint32_t)((((lane >> 3) & 1) * 8 + (lane & 7)) * LDK + ((lane >> 4) * 8)) * 2;

    const int bh = blockIdx.z;
    const int b = bh >> 4, h = bh & 15;
    const int i0 = blockIdx.y * 128;
    const int j0 = blockIdx.x * 128;

    const __half* Q  = g_qk + (size_t)(b * NSEQ + i0) * NQK + h * DH;
    const __half* Kp = g_qk + (size_t)(b * NSEQ + j0) * NQK + HID + h * DH;

    auto stage2 = [&](uint32_t sbase, int k0) {
#pragma unroll
        for (int r = 0; r < 2; r++) {
            int sid = tid + (r << 8);
            int row = sid >> 2, seg = sid & 3;
            uint32_t so = sbase + (uint32_t)(row * (LDK * 2) + seg * 16);
            size_t oq = (size_t)row * NQK + k0 + seg * 8;
            cp_async16(so,          Q  + oq);
            cp_async16(so + 10240u, Kp + oq);
        }
    };

    float acc[2][8][4] = {};

    stage2(sb32,        0);
    stage2(sb32 + SSTG, 32);
    CP_COMMIT();
    cp_wait<0>();
    __syncthreads();

#pragma unroll
    for (int kt = 0; kt < 2; kt++) {
        const uint32_t bQ = sb32 + kt * SSTG, bK = bQ + 10240;
#pragma unroll
        for (int ks = 0; ks < 32; ks += 16) {
            uint32_t aQ[2][4];
#pragma unroll
            for (int mt = 0; mt < 2; mt++) {
                uint32_t ro = (uint32_t)((warp_m * 32 + mt * 16) * LDK + ks) * 2 + ldm_off;
                LDM_X4(aQ[mt], bQ + ro);
            }
#pragma unroll
            for (int c = 0; c < 4; c++) {
                uint32_t bk[4];
                uint32_t ro = (uint32_t)((warp_n * 64 + c * 16) * LDK + ks) * 2 + ldm_off;
                LDM_X4(bk, bK + ro);
#pragma unroll
                for (int half = 0; half < 2; half++) {
                    int nt = c * 2 + half;
#pragma unroll
                    for (int mt = 0; mt < 2; mt++)
                        mma_f16(acc[mt][nt], aQ[mt], bk[half], bk[half + 2]);
                }
            }
        }
    }
    __syncthreads();

    __half* P = g_P + (size_t)bh * NSEQ * NSEQ;
    float cs[8][2];
#pragma unroll
    for (int nt = 0; nt < 8; nt++) { cs[nt][0] = 0.f; cs[nt][1] = 0.f; }

#pragma unroll
    for (int mt = 0; mt < 2; mt++) {
        int r0 = i0 + warp_m * 32 + mt * 16 + g;
#pragma unroll
        for (int nt = 0; nt < 8; nt++) {
            int col = j0 + warp_n * 64 + nt * 8 + ti * 2;
            __half h0 = __float2half(__expf(acc[mt][nt][0] * ATT_SCALE));
            __half h1 = __float2half(__expf(acc[mt][nt][1] * ATT_SCALE));
            __half h2 = __float2half(__expf(acc[mt][nt][2] * ATT_SCALE));
            __half h3 = __float2half(__expf(acc[mt][nt][3] * ATT_SCALE));
            cs[nt][0] += __half2float(h0) + __half2float(h2);
            cs[nt][1] += __half2float(h1) + __half2float(h3);
            __half2 w0; w0.x = h0; w0.y = h1;
            __half2 w1; w1.x = h2; w1.y = h3;
            *(__half2*)(P + (size_t)r0 * NSEQ + col)       = w0;
            *(__half2*)(P + (size_t)(r0 + 8) * NSEQ + col) = w1;
        }
    }

#pragma unroll
    for (int nt = 0; nt < 8; nt++) {
#pragma unroll
        for (int e = 0; e < 2; e++) {
            float v = cs[nt][e];
            v += __shfl_xor_sync(0xFFFFFFFF, v, 4);
            v += __shfl_xor_sync(0xFFFFFFFF, v, 8);
            v += __shfl_xor_sync(0xFFFFFFFF, v, 16);
            cs[nt][e] = v;
        }
    }
    float* spart = (float*)smem;
    if (g == 0) {
#pragma unroll
        for (int nt = 0; nt < 8; nt++) {
            spart[warp_m * 128 + warp_n * 64 + nt * 8 + ti * 2]     = cs[nt][0];
            spart[warp_m * 128 + warp_n * 64 + nt * 8 + ti * 2 + 1] = cs[nt][1];
        }
    }
    __syncthreads();
    if (tid < 128) {
        float s = spart[tid] + spart[128 + tid] + spart[256 + tid] + spart[384 + tid];
        g_pcs[((size_t)bh * NITILE + blockIdx.y) * NSEQ + j0 + tid] = s;
    }
}

// =====================================================================
// rsum: rl[bh][j] = 1 / sum_itile pcs
// =====================================================================
__global__ void rsum_kernel() {
    const int bh = blockIdx.y;
    const int j = blockIdx.x * 256 + threadIdx.x;
    const float* p = g_pcs + (size_t)bh * NITILE * NSEQ + j;
    float s = 0.f;
#pragma unroll
    for (int t = 0; t < NITILE; t++) s += p[(size_t)t * NSEQ];
    g_rl[bh * NSEQ + j] = 1.0f / s;
}

// =====================================================================
// av: Y = P_fp16 @ diag(rl) V_fp16, 1-pass fp16, 64-j iterations.
// Now 3 CTAs/SM (acc footprint small; smem 3x30KB fits).
// =====================================================================
__global__ __launch_bounds__(256, 3) void av_mma() {
    __shared__ __align__(16) char sm[30720];
    const uint32_t smP = smem_u32(sm);
    const uint32_t smV = smP + 20480;
    char* smVc = sm + 20480;

    const int tid = threadIdx.x, lane = tid & 31, wid = tid >> 5;
    const int g = lane >> 2, ti = lane & 3;
    const uint32_t ldm_off =
        (uint32_t)((((lane >> 3) & 1) * 8 + (lane & 7)) * LDK + ((lane >> 4) * 8)) * 2;

    const int bh = blockIdx.y;
    const int b = bh >> 4, h = bh & 15;
    const int i0 = blockIdx.x * 128;

    const __half* Pg = g_P + (size_t)bh * NSEQ * NSEQ + (size_t)i0 * NSEQ;
    const __half* Vbase = g_v + (size_t)(b * NSEQ) * HID + h * DH;
    const float* rl = g_rl + bh * NSEQ;

    const int jl = tid >> 3;            // 0..31  (V row within sub-tile)
    const int d0 = (tid & 7) * 8;       // V col group

    float acc[8][4] = {};

    for (int j0 = 0; j0 < NSEQ; j0 += 64) {
#pragma unroll
        for (int hf = 0; hf < 2; hf++) {
#pragma unroll
            for (int r = 0; r < 2; r++) {
                int sid = tid + (r << 8);
                int row = sid >> 2, seg = sid & 3;
                uint32_t so = (uint32_t)(hf * 10240 + row * (LDK * 2) + seg * 16);
                cp_async16(smP + so,
                           Pg + (size_t)row * NSEQ + j0 + hf * 32 + seg * 8);
            }
        }
        CP_COMMIT();
#pragma unroll
        for (int hf = 0; hf < 2; hf++) {
            const float inv = rl[j0 + hf * 32 + jl];
            const __half* Vr = Vbase + (size_t)(j0 + hf * 32 + jl) * HID + d0;
            __half2 v4[4];
            *(float4*)v4 = *(const float4*)Vr;
            char* vb = smVc + hf * 5120;
#pragma unroll
            for (int e = 0; e < 4; e++) {
                float lo = __half2float(v4[e].x) * inv;
                float hi = __half2float(v4[e].y) * inv;
                int off0 = ((d0 + e * 2)     * LDK + jl) * 2;
                int off1 = ((d0 + e * 2 + 1) * LDK + jl) * 2;
                *(__half*)(vb + off0) = __float2half(lo);
                *(__half*)(vb + off1) = __float2half(hi);
            }
        }
        cp_wait<0>();
        __syncthreads();

#pragma unroll
        for (int hf = 0; hf < 2; hf++) {
            const uint32_t Pst = smP + hf * 10240;
            const uint32_t Vst = smV + hf * 5120;
#pragma unroll
            for (int ks = 0; ks < 32; ks += 16) {
                uint32_t aP[4];
                uint32_t ro = (uint32_t)((wid * 16) * LDK + ks) * 2 + ldm_off;
                LDM_X4(aP, Pst + ro);
#pragma unroll
                for (int c = 0; c < 4; c++) {
                    uint32_t bv[4];
                    uint32_t rb = (uint32_t)((c * 16) * LDK + ks) * 2 + ldm_off;
                    LDM_X4(bv, Vst + rb);
#pragma unroll
                    for (int half = 0; half < 2; half++)
                        mma_f16(acc[c * 2 + half], aP, bv[half], bv[half + 2]);
                }
            }
        }
        __syncthreads();
    }

    const int irow = i0 + wid * 16 + g;
#pragma unroll
    for (int nt = 0; nt < 8; nt++) {
        int d = nt * 8 + ti * 2;
        size_t o0 = (size_t)(b * NSEQ + irow) * HID + h * DH + d;
        size_t o1 = (size_t)(b * NSEQ + irow + 8) * HID + h * DH + d;
        __half2 w0; w0.x = __float2half(acc[nt][0]); w0.y = __float2half(acc[nt][1]);
        __half2 w1; w1.x = __float2half(acc[nt][2]); w1.y = __float2half(acc[nt][3]);
        *(__half2*)(g_y + o0) = w0;
        *(__half2*)(g_y + o1) = w1;
    }
}

// =====================================================================
// out-proj: out = y_fp16 @ (w_out^T fp16 hi/lo)^T + bias. 2-pass fp16,
// 3-stage, 1 barrier/chunk. (round-16 measured-best)
// =====================================================================
__global__ __launch_bounds__(256, 2) void out_gemm(float* __restrict__ C,
                                                   const float* __restrict__ bias) {
    extern __shared__ char smem[];
    const uint32_t sb32 = smem_u32(smem);
    const int tid = threadIdx.x, lane = tid & 31, wid = tid >> 5;
    const int warp_m = wid & 3, warp_n = wid >> 2;
    const int g = lane >> 2, ti = lane & 3;
    const uint32_t ldm_off =
        (uint32_t)((((lane >> 3) & 1) * 8 + (lane & 7)) * LDK + ((lane >> 4) * 8)) * 2;
    const int bm = blockIdx.y * 128, bn = blockIdx.x * 128;
    const int K = HID, N = DIMIN;

    const __half* A0  = g_y   + (size_t)bm * K;
    const __half* Bh0 = g_woh + (size_t)bn * K;
    const __half* Bl0 = g_wol + (size_t)bn * K;

    float acc[2][8][4] = {};
    const int NT = K >> 5;

    auto stage = [&](uint32_t sbase, int k0) {
#pragma unroll
        for (int r = 0; r < 2; r++) {
            int sid = tid + (r << 8);
            int row = sid >> 2, seg = sid & 3;
            uint32_t so = sbase + (uint32_t)(row * (LDK * 2) + seg * 16);
            size_t oa = (size_t)row * K + k0 + seg * 8;
            cp_async16(so,          A0  + oa);
            cp_async16(so + 10240u, Bh0 + oa);
            cp_async16(so + 20480u, Bl0 + oa);
        }
    };

    stage(sb32,        0);  CP_COMMIT();
    stage(sb32 + GSTG, 32); CP_COMMIT();

    for (int kt = 0; kt < NT; kt++) {
        cp_wait<1>();
        __syncthreads();
        if (kt + 2 < NT) stage(sb32 + ((kt + 2) % 3) * GSTG, (kt + 2) << 5);
        CP_COMMIT();

        const uint32_t sb = sb32 + (kt % 3) * GSTG;
        const uint32_t bA = sb, bBh = sb + 10240, bBl = sb + 20480;
#pragma unroll
        for (int ks = 0; ks < 32; ks += 16) {
            uint32_t aF[2][4];
#pragma unroll
            for (int mt = 0; mt < 2; mt++) {
                uint32_t ro = (uint32_t)((warp_m * 32 + mt * 16) * LDK + ks) * 2 + ldm_off;
                LDM_X4(aF[mt], bA + ro);
            }
#pragma unroll
            for (int c = 0; c < 4; c++) {
                uint32_t bh[4], bl[4];
                uint32_t ro = (uint32_t)((warp_n * 64 + c * 16) * LDK + ks) * 2 + ldm_off;
                LDM_X4(bh, bBh + ro);
                LDM_X4(bl, bBl + ro);
#pragma unroll
                for (int half = 0; half < 2; half++) {
                    int nt = c * 2 + half;
#pragma unroll
                    for (int mt = 0; mt < 2; mt++) {
                        mma_f16(acc[mt][nt], aF[mt], bh[half], bh[half + 2]);
                        mma_f16(acc[mt][nt], aF[mt], bl[half], bl[half + 2]);
                    }
                }
            }
        }
    }

#pragma unroll
    for (int mt = 0; mt < 2; mt++) {
        int r0 = bm + warp_m * 32 + mt * 16 + g;
#pragma unroll
        for (int nt = 0; nt < 8; nt++) {
            int col = bn + warp_n * 64 + nt * 8 + ti * 2;
            float2 bb = *(const float2*)(bias + col);
            *(float2*)(C + (size_t)r0 * N + col) =
                make_float2(acc[mt][nt][0] + bb.x, acc[mt][nt][1] + bb.y);
            *(float2*)(C + (size_t)(r0 + 8) * N + col) =
                make_float2(acc[mt][nt][2] + bb.x, acc[mt][nt][3] + bb.y);
        }
    }
}

// =====================================================================
// convert fp32 -> fp16 (elementwise)
// =====================================================================
__global__ void tofp16_kernel(const float* __restrict__ in,
                              __half* __restrict__ out, size_t n4) {
    size_t i = (size_t)blockIdx.x * blockDim.x + threadIdx.x;
    if (i >= n4) return;
    float4 v = ((const float4*)in)[i];
    __half2 a, b;
    a.x = __float2half(v.x); a.y = __float2half(v.y);
    b.x = __float2half(v.z); b.y = __float2half(v.w);
    ((__half2*)out)[i * 2 + 0] = a;
    ((__half2*)out)[i * 2 + 1] = b;
}

// transpose + split to fp16 hi/lo: w[K,N] fp32 -> th/tl [N,K]
__global__ void transpose_split_f16(const float* __restrict__ w,
                                    __half* __restrict__ th,
                                    __half* __restrict__ tl,
                                    int K, int N) {
    __shared__ float tile[32][33];
    const int k0 = blockIdx.y * 32;
    const int n0 = blockIdx.x * 32;
    const int tx = threadIdx.x, ty = threadIdx.y;   // (32,8)
#pragma unroll
    for (int r = 0; r < 4; r++)
        tile[ty + 8 * r][tx] = w[(size_t)(k0 + ty + 8 * r) * N + n0 + tx];
    __syncthreads();
#pragma unroll
    for (int r = 0; r < 4; r++) {
        const int n = n0 + ty + 8 * r;
        const int k = k0 + tx;
        float v = tile[tx][ty + 8 * r];
        __half hh = __float2half(v);
        th[(size_t)n * K + k] = hh;
        tl[(size_t)n * K + k] = __float2half(v - __half2float(hh));
    }
}

// ---------------------------------------------------------------------
extern "C" void kernel_launch(void* const* d_in, const int* in_sizes, int n_in,
                              void* d_out, int out_size) {
    const float* x     = (const float*)d_in[0];
    const float* w_qkv = (const float*)d_in[1];
    const float* w_out = (const float*)d_in[2];
    const float* b_out = (const float*)d_in[3];
    float* out = (float*)d_out;

    cudaFuncSetAttribute(qkv_gemm,
                         cudaFuncAttributeMaxDynamicSharedMemorySize, QDSMEM);
    cudaFuncSetAttribute(scores_mma,
                         cudaFuncAttributeMaxDynamicSharedMemorySize, SC_SMEM);
    cudaFuncSetAttribute(out_gemm,
                         cudaFuncAttributeMaxDynamicSharedMemorySize, ODSMEM);

    void *p_x16, *p_wqh, *p_wql, *p_woh, *p_wol;
    cudaGetSymbolAddress(&p_x16, g_x16);
    cudaGetSymbolAddress(&p_wqh, g_wqh);
    cudaGetSymbolAddress(&p_wql, g_wql);
    cudaGetSymbolAddress(&p_woh, g_woh);
    cudaGetSymbolAddress(&p_wol, g_wol);

    // 0a. x -> fp16
    {
        size_t n4 = (size_t)ROWS * DIMIN / 4;
        tofp16_kernel<<<(unsigned)((n4 + 255) / 256), 256>>>(
            x, (__half*)p_x16, n4);
    }
    // 0b/0c. transpose+split weights -> fp16 hi/lo [N,K]
    transpose_split_f16<<<dim3(QKV_COLS / 32, DIMIN / 32), dim3(32, 8)>>>(
        w_qkv, (__half*)p_wqh, (__half*)p_wql, DIMIN, QKV_COLS);
    transpose_split_f16<<<dim3(HID / 32, DIMIN / 32), dim3(32, 8)>>>(
        w_out, (__half*)p_woh, (__half*)p_wol, DIMIN, HID);

    // 1. QKV projection (2-pass fp16, 2-stage)
    qkv_gemm<<<dim3(QKV_COLS / 128, ROWS / 128), 256, QDSMEM>>>();

    // 2. P = exp(scale * Q K^T) (fp16, 1-pass) + partial column sums
    scores_mma<<<dim3(NSEQ / 128, NSEQ / 128, BH), 256, SC_SMEM>>>();

    // 3. rl = 1 / column sums
    rsum_kernel<<<dim3(NSEQ / 256, BH), 256>>>();

    // 4. Y = P diag(rl) V  -> y fp16  (64-j iterations, 3 CTAs/SM)
    av_mma<<<dim3(NSEQ / 128, BH), 256>>>();

    // 5. out = Y @ w_out + b_out (2-pass fp16, 3-stage)
    out_gemm<<<dim3(HID / 128, ROWS / 128), 256, ODSMEM>>>(out, b_out);
}